// round 1
// baseline (speedup 1.0000x reference)
#include <cuda_runtime.h>

#define BATCH 4096
#define NF    8192
#define DIM   256
#define HEADS 4
#define CELLS 32
#define SPLITK 4

// ---------------- scratch (device globals; no allocs allowed) ----------------
__device__ float g_reps[NF * DIM];                    // 8 MB
__device__ float g_part[SPLITK][BATCH * DIM];         // 16 MB
__device__ float g_hidden[BATCH * DIM];               // 4 MB

// ---------------- f32x2 helpers (packed FFMA2 path, PTX-only) ----------------
__device__ __forceinline__ unsigned long long pack2_dup(float v) {
    unsigned long long r;
    unsigned int u = __float_as_uint(v);
    asm("mov.b64 %0, {%1, %2};" : "=l"(r) : "r"(u), "r"(u));
    return r;
}
__device__ __forceinline__ void fma2(unsigned long long& d,
                                     unsigned long long a,
                                     unsigned long long b) {
    asm("fma.rn.f32x2 %0, %1, %2, %0;" : "+l"(d) : "l"(a), "l"(b));
}
__device__ __forceinline__ void unpack2(unsigned long long v, float& lo, float& hi) {
    unsigned int l, h;
    asm("mov.b64 {%0, %1}, %2;" : "=r"(l), "=r"(h) : "l"(v));
    lo = __uint_as_float(l);
    hi = __uint_as_float(h);
}

// =====================================================================
// Kernel 1: reps[n,:] = latent + sum_h gate-blended codebook rows
// 256 threads/block, 16 rows/block. Router W (128KB) lives in dyn smem.
// =====================================================================
__global__ void reps_kernel(const float* __restrict__ proj,
                            const float* __restrict__ rw,
                            const float* __restrict__ rb,
                            const float* __restrict__ cb) {
    extern __shared__ float Wsh[];              // HEADS*CELLS*DIM floats
    __shared__ float lat[DIM];
    __shared__ float sc[HEADS * CELLS];
    __shared__ float g_sh[HEADS];
    __shared__ int   w_sh[HEADS];
    __shared__ int   r_sh[HEADS];

    const int tid  = threadIdx.x;
    const int lane = tid & 31;
    const int warp = tid >> 5;

    for (int i = tid; i < HEADS * CELLS * DIM; i += 256)
        Wsh[i] = rw[i];
    __syncthreads();

    const int row0 = blockIdx.x * 16;
    for (int r = 0; r < 16; ++r) {
        const int row = row0 + r;
        lat[tid] = proj[row * DIM + tid];
        __syncthreads();

        // cache this lane's 8 latent entries
        float la[8];
        #pragma unroll
        for (int i = 0; i < 8; ++i) la[i] = lat[lane + 32 * i];

        // scores: each warp handles 16 (h,c) pairs
        #pragma unroll 1
        for (int pi = 0; pi < 16; ++pi) {
            const int p = warp * 16 + pi;
            const float* wrow = &Wsh[p * DIM];
            float m = -3.4e38f;
            #pragma unroll
            for (int i = 0; i < 8; ++i)
                m = fmaxf(m, la[i] + wrow[lane + 32 * i]);
            #pragma unroll
            for (int off = 16; off >= 1; off >>= 1)
                m = fmaxf(m, __shfl_xor_sync(0xffffffffu, m, off));
            if (lane == 0) sc[p] = m + rb[p];
        }
        __syncthreads();

        // top-2 per head (warps 0..3), jax tie-break = lowest index
        if (warp < HEADS) {
            const float s = sc[warp * CELLS + lane];
            float v = s; int idx = lane;
            #pragma unroll
            for (int off = 16; off >= 1; off >>= 1) {
                float ov = __shfl_xor_sync(0xffffffffu, v, off);
                int   oi = __shfl_xor_sync(0xffffffffu, idx, off);
                if (ov > v || (ov == v && oi < idx)) { v = ov; idx = oi; }
            }
            const float v1 = v; const int i1 = idx;
            v = (lane == i1) ? -3.4e38f : s; idx = lane;
            #pragma unroll
            for (int off = 16; off >= 1; off >>= 1) {
                float ov = __shfl_xor_sync(0xffffffffu, v, off);
                int   oi = __shfl_xor_sync(0xffffffffu, idx, off);
                if (ov > v || (ov == v && oi < idx)) { v = ov; idx = oi; }
            }
            if (lane == 0) {
                g_sh[warp] = 1.0f / (1.0f + expf(-(v1 - v)));
                w_sh[warp] = i1;
                r_sh[warp] = idx;
            }
        }
        __syncthreads();

        float acc = lat[tid];
        #pragma unroll
        for (int h = 0; h < HEADS; ++h) {
            const float g = g_sh[h];
            acc += g          * cb[(h * CELLS + w_sh[h]) * DIM + tid]
                 + (1.0f - g) * cb[(h * CELLS + r_sh[h]) * DIM + tid];
        }
        g_reps[row * DIM + tid] = acc;
        __syncthreads();
    }
}

// =====================================================================
// Kernel 2: partial[bz] = X[:, kchunk] @ reps[kchunk, :]   (split-K=4)
// BM=128 BN=64 BK=16, 256 thr, per-thread 8(M, as 4 f32x2 pairs) x 4(N)
// =====================================================================
__global__ void __launch_bounds__(256) gemm2_kernel(const float* __restrict__ X) {
    const int KC = NF / SPLITK;                 // 2048
    const int bm = blockIdx.x, bn = blockIdx.y, bz = blockIdx.z;
    const int k0 = bz * KC;
    const int tid = threadIdx.x;
    const int tx = tid & 15;                    // 4 N-cols
    const int ty = tid >> 4;                    // 8 M-rows (4 pairs)

    __shared__ __align__(16) float As[2][16][128];
    __shared__ __align__(16) unsigned long long Bs[2][16][64];

    unsigned long long acc[4][4];
    #pragma unroll
    for (int i = 0; i < 4; ++i)
        #pragma unroll
        for (int j = 0; j < 4; ++j) acc[i][j] = 0ull;

    const float* Xb = X + (size_t)(bm * 128) * NF + k0;
    const float* Rb = g_reps + (size_t)k0 * DIM + bn * 64;

    const int ar = tid >> 2;            // 0..63 (A row, +64 second)
    const int ac = (tid & 3) * 4;       // A k-col
    const int br = tid >> 4;            // 0..15 (B k-row)
    const int bc = (tid & 15) * 4;      // B n-col

    // preload tile 0
    float4 a0 = *(const float4*)&Xb[(size_t)ar * NF + ac];
    float4 a1 = *(const float4*)&Xb[(size_t)(ar + 64) * NF + ac];
    float4 b0 = *(const float4*)&Rb[br * DIM + bc];
    #pragma unroll
    for (int j = 0; j < 4; ++j) {
        As[0][ac + j][ar]      = ((const float*)&a0)[j];
        As[0][ac + j][ar + 64] = ((const float*)&a1)[j];
    }
    Bs[0][br][bc + 0] = pack2_dup(b0.x);
    Bs[0][br][bc + 1] = pack2_dup(b0.y);
    Bs[0][br][bc + 2] = pack2_dup(b0.z);
    Bs[0][br][bc + 3] = pack2_dup(b0.w);
    __syncthreads();

    const int NT = KC / 16;             // 128
    for (int t = 0; t < NT; ++t) {
        const int cur = t & 1, nxt = cur ^ 1;
        float4 na0, na1, nb0;
        if (t + 1 < NT) {
            const float* Xt = Xb + (t + 1) * 16;
            na0 = *(const float4*)&Xt[(size_t)ar * NF + ac];
            na1 = *(const float4*)&Xt[(size_t)(ar + 64) * NF + ac];
            nb0 = *(const float4*)&Rb[((t + 1) * 16 + br) * DIM + bc];
        }
        #pragma unroll
        for (int k = 0; k < 16; ++k) {
            const ulonglong2* ap = (const ulonglong2*)&As[cur][k][ty * 8];
            ulonglong2 a01 = ap[0], a23 = ap[1];
            const ulonglong2* bp = (const ulonglong2*)&Bs[cur][k][tx * 4];
            ulonglong2 b01 = bp[0], b23 = bp[1];
            unsigned long long a_[4] = {a01.x, a01.y, a23.x, a23.y};
            unsigned long long b_[4] = {b01.x, b01.y, b23.x, b23.y};
            #pragma unroll
            for (int i = 0; i < 4; ++i)
                #pragma unroll
                for (int j = 0; j < 4; ++j) fma2(acc[i][j], a_[i], b_[j]);
        }
        if (t + 1 < NT) {
            #pragma unroll
            for (int j = 0; j < 4; ++j) {
                As[nxt][ac + j][ar]      = ((const float*)&na0)[j];
                As[nxt][ac + j][ar + 64] = ((const float*)&na1)[j];
            }
            Bs[nxt][br][bc + 0] = pack2_dup(nb0.x);
            Bs[nxt][br][bc + 1] = pack2_dup(nb0.y);
            Bs[nxt][br][bc + 2] = pack2_dup(nb0.z);
            Bs[nxt][br][bc + 3] = pack2_dup(nb0.w);
        }
        __syncthreads();
    }

    float* P = g_part[bz];
    const int m0 = bm * 128 + ty * 8;
    const int n0 = bn * 64 + tx * 4;
    #pragma unroll
    for (int i = 0; i < 4; ++i) {
        float lo[4], hi[4];
        #pragma unroll
        for (int j = 0; j < 4; ++j) unpack2(acc[i][j], lo[j], hi[j]);
        *(float4*)&P[(m0 + 2 * i) * DIM + n0]     = make_float4(lo[0], lo[1], lo[2], lo[3]);
        *(float4*)&P[(m0 + 2 * i + 1) * DIM + n0] = make_float4(hi[0], hi[1], hi[2], hi[3]);
    }
}

// deterministic split-K reduction
__global__ void reduce_kernel() {
    const int i = blockIdx.x * 256 + threadIdx.x;   // float4 index
    float4 a = ((const float4*)g_part[0])[i];
    float4 b = ((const float4*)g_part[1])[i];
    float4 c = ((const float4*)g_part[2])[i];
    float4 d = ((const float4*)g_part[3])[i];
    float4 s = make_float4(a.x + b.x + c.x + d.x, a.y + b.y + c.y + d.y,
                           a.z + b.z + c.z + d.z, a.w + b.w + c.w + d.w);
    ((float4*)g_hidden)[i] = s;
}

// =====================================================================
// Kernel 3: out = relu(hidden @ reps^T + bias)
// BM=128 BN=128 BK=8, 256 thr, per-thread 8(M pairs) x 8(N)
// =====================================================================
__global__ void __launch_bounds__(256) gemm3_kernel(const float* __restrict__ bias,
                                                    float* __restrict__ out) {
    const int bm = blockIdx.x, bn = blockIdx.y;
    const int tid = threadIdx.x;
    const int tx = tid & 15;                    // 8 N-cols
    const int ty = tid >> 4;                    // 8 M-rows (4 pairs)

    __shared__ __align__(16) float As[2][8][128];
    __shared__ __align__(16) unsigned long long Bs[2][8][128];

    unsigned long long acc[4][8];
    #pragma unroll
    for (int i = 0; i < 4; ++i)
        #pragma unroll
        for (int j = 0; j < 8; ++j) acc[i][j] = 0ull;

    const float* Ab = g_hidden + (size_t)(bm * 128) * DIM;
    const float* Rb = g_reps + (size_t)(bn * 128) * DIM;

    const int ar = tid >> 1;            // 0..127
    const int ac = (tid & 1) * 4;       // 0 or 4

    float4 a0 = *(const float4*)&Ab[ar * DIM + ac];
    float4 b0 = *(const float4*)&Rb[ar * DIM + ac];
    #pragma unroll
    for (int j = 0; j < 4; ++j) {
        As[0][ac + j][ar] = ((const float*)&a0)[j];
        Bs[0][ac + j][ar] = pack2_dup(((const float*)&b0)[j]);
    }
    __syncthreads();

    const int NT = DIM / 8;             // 32
    for (int t = 0; t < NT; ++t) {
        const int cur = t & 1, nxt = cur ^ 1;
        float4 na0, nb0;
        if (t + 1 < NT) {
            na0 = *(const float4*)&Ab[ar * DIM + (t + 1) * 8 + ac];
            nb0 = *(const float4*)&Rb[ar * DIM + (t + 1) * 8 + ac];
        }
        #pragma unroll
        for (int k = 0; k < 8; ++k) {
            const ulonglong2* ap = (const ulonglong2*)&As[cur][k][ty * 8];
            ulonglong2 a01 = ap[0], a23 = ap[1];
            const ulonglong2* bp = (const ulonglong2*)&Bs[cur][k][tx * 8];
            ulonglong2 b01 = bp[0], b23 = bp[1], b45 = bp[2], b67 = bp[3];
            unsigned long long a_[4] = {a01.x, a01.y, a23.x, a23.y};
            unsigned long long b_[8] = {b01.x, b01.y, b23.x, b23.y,
                                        b45.x, b45.y, b67.x, b67.y};
            #pragma unroll
            for (int i = 0; i < 4; ++i)
                #pragma unroll
                for (int j = 0; j < 8; ++j) fma2(acc[i][j], a_[i], b_[j]);
        }
        if (t + 1 < NT) {
            #pragma unroll
            for (int j = 0; j < 4; ++j) {
                As[nxt][ac + j][ar] = ((const float*)&na0)[j];
                Bs[nxt][ac + j][ar] = pack2_dup(((const float*)&nb0)[j]);
            }
        }
        __syncthreads();
    }

    const int m0 = bm * 128 + ty * 8;
    const int n0 = bn * 128 + tx * 8;
    float bi[8];
    *(float4*)&bi[0] = *(const float4*)&bias[n0];
    *(float4*)&bi[4] = *(const float4*)&bias[n0 + 4];

    #pragma unroll
    for (int i = 0; i < 4; ++i) {
        float lo[8], hi[8];
        #pragma unroll
        for (int j = 0; j < 8; ++j) {
            unpack2(acc[i][j], lo[j], hi[j]);
            lo[j] = fmaxf(lo[j] + bi[j], 0.0f);
            hi[j] = fmaxf(hi[j] + bi[j], 0.0f);
        }
        float* r0 = &out[(size_t)(m0 + 2 * i) * NF + n0];
        float* r1 = &out[(size_t)(m0 + 2 * i + 1) * NF + n0];
        *(float4*)&r0[0] = make_float4(lo[0], lo[1], lo[2], lo[3]);
        *(float4*)&r0[4] = make_float4(lo[4], lo[5], lo[6], lo[7]);
        *(float4*)&r1[0] = make_float4(hi[0], hi[1], hi[2], hi[3]);
        *(float4*)&r1[4] = make_float4(hi[4], hi[5], hi[6], hi[7]);
    }
}

// =====================================================================
extern "C" void kernel_launch(void* const* d_in, const int* in_sizes, int n_in,
                              void* d_out, int out_size) {
    const float* x    = (const float*)d_in[0];
    const float* proj = (const float*)d_in[1];
    const float* rw   = (const float*)d_in[2];
    const float* rb   = (const float*)d_in[3];
    const float* cb   = (const float*)d_in[4];
    const float* bias = (const float*)d_in[5];
    float* out = (float*)d_out;

    const int wbytes = HEADS * CELLS * DIM * (int)sizeof(float);   // 128 KB
    cudaFuncSetAttribute((const void*)reps_kernel,
                         cudaFuncAttributeMaxDynamicSharedMemorySize, wbytes);
    reps_kernel<<<NF / 16, 256, wbytes>>>(proj, rw, rb, cb);

    dim3 g2(BATCH / 128, DIM / 64, SPLITK);
    gemm2_kernel<<<g2, 256>>>(x);

    reduce_kernel<<<(BATCH * DIM / 4) / 256, 256>>>();

    dim3 g3(BATCH / 128, NF / 128);
    gemm3_kernel<<<g3, 256>>>(bias, out);
}

// round 4
// speedup vs baseline: 1.8385x; 1.8385x over previous
#include <cuda_runtime.h>

#define BATCH 4096
#define NF    8192
#define DIM   256
#define HEADS 4
#define CELLS 32
#define SPLITK 8

// ---------------- scratch (device globals; no allocs allowed) ----------------
__device__ float g_reps[NF * DIM];                    // 8 MB
__device__ float g_part[SPLITK][BATCH * DIM];         // 32 MB
__device__ float g_hidden[BATCH * DIM];               // 4 MB

// ---------------- f32x2 helpers (packed FFMA2 path, PTX-only) ----------------
__device__ __forceinline__ unsigned long long pack2_dup(float v) {
    unsigned long long r;
    unsigned int u = __float_as_uint(v);
    asm("mov.b64 %0, {%1, %2};" : "=l"(r) : "r"(u), "r"(u));
    return r;
}
__device__ __forceinline__ void fma2(unsigned long long& d,
                                     unsigned long long a,
                                     unsigned long long b) {
    asm("fma.rn.f32x2 %0, %1, %2, %0;" : "+l"(d) : "l"(a), "l"(b));
}
__device__ __forceinline__ void unpack2(unsigned long long v, float& lo, float& hi) {
    unsigned int l, h;
    asm("mov.b64 {%0, %1}, %2;" : "=r"(l), "=r"(h) : "l"(v));
    lo = __uint_as_float(l);
    hi = __uint_as_float(h);
}

// 16-byte-chunk XOR swizzle (injective, stays within the row).
// c is a 16B-chunk index; flips bit0 on every odd 128-byte half.
__device__ __forceinline__ int swc(int c) { return c ^ ((c >> 3) & 1); }

// =====================================================================
// Kernel 1: reps[n,:] = latent + sum_h gate-blended codebook rows
// =====================================================================
__global__ void reps_kernel(const float* __restrict__ proj,
                            const float* __restrict__ rw,
                            const float* __restrict__ rb,
                            const float* __restrict__ cb) {
    extern __shared__ float Wsh[];              // HEADS*CELLS*DIM floats
    __shared__ float lat[DIM];
    __shared__ float sc[HEADS * CELLS];
    __shared__ float g_sh[HEADS];
    __shared__ int   w_sh[HEADS];
    __shared__ int   r_sh[HEADS];

    const int tid  = threadIdx.x;
    const int lane = tid & 31;
    const int warp = tid >> 5;

    for (int i = tid; i < HEADS * CELLS * DIM; i += 256)
        Wsh[i] = rw[i];
    __syncthreads();

    const int row0 = blockIdx.x * 16;
    for (int r = 0; r < 16; ++r) {
        const int row = row0 + r;
        lat[tid] = proj[row * DIM + tid];
        __syncthreads();

        float la[8];
        #pragma unroll
        for (int i = 0; i < 8; ++i) la[i] = lat[lane + 32 * i];

        #pragma unroll 1
        for (int pi = 0; pi < 16; ++pi) {
            const int p = warp * 16 + pi;
            const float* wrow = &Wsh[p * DIM];
            float m = -3.4e38f;
            #pragma unroll
            for (int i = 0; i < 8; ++i)
                m = fmaxf(m, la[i] + wrow[lane + 32 * i]);
            #pragma unroll
            for (int off = 16; off >= 1; off >>= 1)
                m = fmaxf(m, __shfl_xor_sync(0xffffffffu, m, off));
            if (lane == 0) sc[p] = m + rb[p];
        }
        __syncthreads();

        if (warp < HEADS) {
            const float s = sc[warp * CELLS + lane];
            float v = s; int idx = lane;
            #pragma unroll
            for (int off = 16; off >= 1; off >>= 1) {
                float ov = __shfl_xor_sync(0xffffffffu, v, off);
                int   oi = __shfl_xor_sync(0xffffffffu, idx, off);
                if (ov > v || (ov == v && oi < idx)) { v = ov; idx = oi; }
            }
            const float v1 = v; const int i1 = idx;
            v = (lane == i1) ? -3.4e38f : s; idx = lane;
            #pragma unroll
            for (int off = 16; off >= 1; off >>= 1) {
                float ov = __shfl_xor_sync(0xffffffffu, v, off);
                int   oi = __shfl_xor_sync(0xffffffffu, idx, off);
                if (ov > v || (ov == v && oi < idx)) { v = ov; idx = oi; }
            }
            if (lane == 0) {
                g_sh[warp] = 1.0f / (1.0f + expf(-(v1 - v)));
                w_sh[warp] = i1;
                r_sh[warp] = idx;
            }
        }
        __syncthreads();

        float acc = lat[tid];
        #pragma unroll
        for (int h = 0; h < HEADS; ++h) {
            const float g = g_sh[h];
            acc += g          * cb[(h * CELLS + w_sh[h]) * DIM + tid]
                 + (1.0f - g) * cb[(h * CELLS + r_sh[h]) * DIM + tid];
        }
        g_reps[row * DIM + tid] = acc;
        __syncthreads();
    }
}

// =====================================================================
// Kernel 2: partial[bz] = X[:, kchunk] @ reps[kchunk, :]   (split-K=8)
// BM=128 BN=128 BK=8, 256 thr. Warp: 64Mx32N. Thread: 8M(4 pairs) x 8N.
// A rows: 128 floats (32 chunks), B rows: 128 ull (64 chunks); both
// stored/loaded through the swc() chunk swizzle -> conflict-free LDS.128.
// =====================================================================
__global__ void __launch_bounds__(256, 2) gemm2_kernel(const float* __restrict__ X) {
    const int KC = NF / SPLITK;                 // 1024
    const int bm = blockIdx.x, bn = blockIdx.y, bz = blockIdx.z;
    const int k0 = bz * KC;
    const int tid = threadIdx.x;
    const int lane = tid & 31, warp = tid >> 5;
    const int warp_m = warp & 1, warp_n = warp >> 1;       // 2 x 4 warps
    const int lane_m = lane >> 2, lane_n = lane & 3;       // 8 x 4 lanes

    __shared__ __align__(16) float As[2][8][128];
    __shared__ __align__(16) unsigned long long Bs[2][8][128];

    unsigned long long acc[4][8];
    #pragma unroll
    for (int i = 0; i < 4; ++i)
        #pragma unroll
        for (int j = 0; j < 8; ++j) acc[i][j] = 0ull;

    const float* Xb = X + (size_t)(bm * 128) * NF + k0;
    const float* Rb = g_reps + (size_t)k0 * DIM + bn * 128;

    // global->smem mapping
    const int ar = tid >> 1;             // 0..127 (M row)
    const int ac = (tid & 1) * 4;        // k offset 0 or 4
    const int ars = (swc(ar >> 2) << 2) | (ar & 3);   // swizzled float idx
    const int br = tid >> 5;             // 0..7   (k row)
    const int bl = tid & 31;             // lane covers 4 ull = 2 chunks
    const int bs0 = swc(bl * 2) << 1;    // swizzled ull idx of chunk 0
    const int bs1 = swc(bl * 2 + 1) << 1;

    // fragment read bases (loop-invariant, swizzled)
    const int am0 = warp_m * 64 + lane_m * 8;         // float idx
    const int aF0 = swc((am0 >> 2)) << 2;
    const int aF1 = swc((am0 >> 2) + 1) << 2;
    const int cB = (warp_n * 32 + lane_n * 8) >> 1;   // chunk base
    const int bF0 = swc(cB) << 1;
    const int bF1 = swc(cB + 1) << 1;
    const int bF2 = swc(cB + 2) << 1;
    const int bF3 = swc(cB + 3) << 1;

    // preload tile 0
    {
        float4 a0 = *(const float4*)&Xb[(size_t)ar * NF + ac];
        float4 b0 = *(const float4*)&Rb[br * DIM + bl * 4];
        #pragma unroll
        for (int j = 0; j < 4; ++j) As[0][ac + j][ars] = ((const float*)&a0)[j];
        ulonglong2 p0; p0.x = pack2_dup(b0.x); p0.y = pack2_dup(b0.y);
        ulonglong2 p1; p1.x = pack2_dup(b0.z); p1.y = pack2_dup(b0.w);
        *(ulonglong2*)&Bs[0][br][bs0] = p0;
        *(ulonglong2*)&Bs[0][br][bs1] = p1;
    }
    __syncthreads();

    const int NT = KC / 8;               // 128
    for (int t = 0; t < NT; ++t) {
        const int cur = t & 1, nxt = cur ^ 1;
        float4 na, nb;
        if (t + 1 < NT) {
            na = *(const float4*)&Xb[(size_t)ar * NF + (t + 1) * 8 + ac];
            nb = *(const float4*)&Rb[((t + 1) * 8 + br) * DIM + bl * 4];
        }
        #pragma unroll
        for (int k = 0; k < 8; ++k) {
            ulonglong2 a01 = *(const ulonglong2*)&As[cur][k][aF0];
            ulonglong2 a23 = *(const ulonglong2*)&As[cur][k][aF1];
            ulonglong2 b01 = *(const ulonglong2*)&Bs[cur][k][bF0];
            ulonglong2 b23 = *(const ulonglong2*)&Bs[cur][k][bF1];
            ulonglong2 b45 = *(const ulonglong2*)&Bs[cur][k][bF2];
            ulonglong2 b67 = *(const ulonglong2*)&Bs[cur][k][bF3];
            unsigned long long a_[4] = {a01.x, a01.y, a23.x, a23.y};
            unsigned long long b_[8] = {b01.x, b01.y, b23.x, b23.y,
                                        b45.x, b45.y, b67.x, b67.y};
            #pragma unroll
            for (int i = 0; i < 4; ++i)
                #pragma unroll
                for (int j = 0; j < 8; ++j) fma2(acc[i][j], a_[i], b_[j]);
        }
        if (t + 1 < NT) {
            #pragma unroll
            for (int j = 0; j < 4; ++j) As[nxt][ac + j][ars] = ((const float*)&na)[j];
            ulonglong2 p0; p0.x = pack2_dup(nb.x); p0.y = pack2_dup(nb.y);
            ulonglong2 p1; p1.x = pack2_dup(nb.z); p1.y = pack2_dup(nb.w);
            *(ulonglong2*)&Bs[nxt][br][bs0] = p0;
            *(ulonglong2*)&Bs[nxt][br][bs1] = p1;
        }
        __syncthreads();
    }

    float* P = g_part[bz];
    const int m0 = bm * 128 + am0;
    const int n0 = bn * 128 + warp_n * 32 + lane_n * 8;
    #pragma unroll
    for (int i = 0; i < 4; ++i) {
        float lo[8], hi[8];
        #pragma unroll
        for (int j = 0; j < 8; ++j) unpack2(acc[i][j], lo[j], hi[j]);
        float* r0 = &P[(m0 + 2 * i) * DIM + n0];
        float* r1 = &P[(m0 + 2 * i + 1) * DIM + n0];
        *(float4*)&r0[0] = make_float4(lo[0], lo[1], lo[2], lo[3]);
        *(float4*)&r0[4] = make_float4(lo[4], lo[5], lo[6], lo[7]);
        *(float4*)&r1[0] = make_float4(hi[0], hi[1], hi[2], hi[3]);
        *(float4*)&r1[4] = make_float4(hi[4], hi[5], hi[6], hi[7]);
    }
}

// deterministic split-K reduction (8-way)
__global__ void reduce_kernel() {
    const int i = blockIdx.x * 256 + threadIdx.x;   // float4 index
    float4 s = ((const float4*)g_part[0])[i];
    #pragma unroll
    for (int z = 1; z < SPLITK; ++z) {
        float4 p = ((const float4*)g_part[z])[i];
        s.x += p.x; s.y += p.y; s.z += p.z; s.w += p.w;
    }
    ((float4*)g_hidden)[i] = s;
}

// =====================================================================
// Kernel 3: out = relu(hidden @ reps^T + bias)
// BM=128 BN=128 BK=8, 256 thr. Warp: 64Mx32N. Thread: 8M(4 pairs) x 8N.
// =====================================================================
__global__ void __launch_bounds__(256, 2) gemm3_kernel(const float* __restrict__ bias,
                                                       float* __restrict__ out) {
    const int bm = blockIdx.x, bn = blockIdx.y;
    const int tid = threadIdx.x;
    const int lane = tid & 31, warp = tid >> 5;
    const int warp_m = warp & 1, warp_n = warp >> 1;
    const int lane_m = lane >> 2, lane_n = lane & 3;

    __shared__ __align__(16) float As[2][8][128];
    __shared__ __align__(16) unsigned long long Bs[2][8][128];

    unsigned long long acc[4][8];
    #pragma unroll
    for (int i = 0; i < 4; ++i)
        #pragma unroll
        for (int j = 0; j < 8; ++j) acc[i][j] = 0ull;

    const float* Ab = g_hidden + (size_t)(bm * 128) * DIM;
    const float* Rb = g_reps + (size_t)(bn * 128) * DIM;

    const int ar = tid >> 1;             // 0..127 (row of A / n-col of B)
    const int ac = (tid & 1) * 4;        // k offset 0 or 4
    const int ars = (swc(ar >> 2) << 2) | (ar & 3);          // A swizzled float idx
    const int brs = (swc(ar >> 1) << 1) | (ar & 1);          // B swizzled ull idx

    const int am0 = warp_m * 64 + lane_m * 8;
    const int aF0 = swc((am0 >> 2)) << 2;
    const int aF1 = swc((am0 >> 2) + 1) << 2;
    const int cB = (warp_n * 32 + lane_n * 8) >> 1;
    const int bF0 = swc(cB) << 1;
    const int bF1 = swc(cB + 1) << 1;
    const int bF2 = swc(cB + 2) << 1;
    const int bF3 = swc(cB + 3) << 1;

    {
        float4 a0 = *(const float4*)&Ab[ar * DIM + ac];
        float4 b0 = *(const float4*)&Rb[ar * DIM + ac];
        #pragma unroll
        for (int j = 0; j < 4; ++j) {
            As[0][ac + j][ars] = ((const float*)&a0)[j];
            Bs[0][ac + j][brs] = pack2_dup(((const float*)&b0)[j]);
        }
    }
    __syncthreads();

    const int NT = DIM / 8;              // 32
    for (int t = 0; t < NT; ++t) {
        const int cur = t & 1, nxt = cur ^ 1;
        float4 na, nb;
        if (t + 1 < NT) {
            na = *(const float4*)&Ab[ar * DIM + (t + 1) * 8 + ac];
            nb = *(const float4*)&Rb[ar * DIM + (t + 1) * 8 + ac];
        }
        #pragma unroll
        for (int k = 0; k < 8; ++k) {
            ulonglong2 a01 = *(const ulonglong2*)&As[cur][k][aF0];
            ulonglong2 a23 = *(const ulonglong2*)&As[cur][k][aF1];
            ulonglong2 b01 = *(const ulonglong2*)&Bs[cur][k][bF0];
            ulonglong2 b23 = *(const ulonglong2*)&Bs[cur][k][bF1];
            ulonglong2 b45 = *(const ulonglong2*)&Bs[cur][k][bF2];
            ulonglong2 b67 = *(const ulonglong2*)&Bs[cur][k][bF3];
            unsigned long long a_[4] = {a01.x, a01.y, a23.x, a23.y};
            unsigned long long b_[8] = {b01.x, b01.y, b23.x, b23.y,
                                        b45.x, b45.y, b67.x, b67.y};
            #pragma unroll
            for (int i = 0; i < 4; ++i)
                #pragma unroll
                for (int j = 0; j < 8; ++j) fma2(acc[i][j], a_[i], b_[j]);
        }
        if (t + 1 < NT) {
            #pragma unroll
            for (int j = 0; j < 4; ++j) {
                As[nxt][ac + j][ars] = ((const float*)&na)[j];
                Bs[nxt][ac + j][brs] = pack2_dup(((const float*)&nb)[j]);
            }
        }
        __syncthreads();
    }

    const int m0 = bm * 128 + am0;
    const int n0 = bn * 128 + warp_n * 32 + lane_n * 8;
    float bi[8];
    *(float4*)&bi[0] = *(const float4*)&bias[n0];
    *(float4*)&bi[4] = *(const float4*)&bias[n0 + 4];

    #pragma unroll
    for (int i = 0; i < 4; ++i) {
        float lo[8], hi[8];
        #pragma unroll
        for (int j = 0; j < 8; ++j) {
            unpack2(acc[i][j], lo[j], hi[j]);
            lo[j] = fmaxf(lo[j] + bi[j], 0.0f);
            hi[j] = fmaxf(hi[j] + bi[j], 0.0f);
        }
        float* r0 = &out[(size_t)(m0 + 2 * i) * NF + n0];
        float* r1 = &out[(size_t)(m0 + 2 * i + 1) * NF + n0];
        *(float4*)&r0[0] = make_float4(lo[0], lo[1], lo[2], lo[3]);
        *(float4*)&r0[4] = make_float4(lo[4], lo[5], lo[6], lo[7]);
        *(float4*)&r1[0] = make_float4(hi[0], hi[1], hi[2], hi[3]);
        *(float4*)&r1[4] = make_float4(hi[4], hi[5], hi[6], hi[7]);
    }
}

// =====================================================================
extern "C" void kernel_launch(void* const* d_in, const int* in_sizes, int n_in,
                              void* d_out, int out_size) {
    const float* x    = (const float*)d_in[0];
    const float* proj = (const float*)d_in[1];
    const float* rw   = (const float*)d_in[2];
    const float* rb   = (const float*)d_in[3];
    const float* cb   = (const float*)d_in[4];
    const float* bias = (const float*)d_in[5];
    float* out = (float*)d_out;

    const int wbytes = HEADS * CELLS * DIM * (int)sizeof(float);   // 128 KB
    cudaFuncSetAttribute((const void*)reps_kernel,
                         cudaFuncAttributeMaxDynamicSharedMemorySize, wbytes);
    reps_kernel<<<NF / 16, 256, wbytes>>>(proj, rw, rb, cb);

    dim3 g2(BATCH / 128, DIM / 128, SPLITK);
    gemm2_kernel<<<g2, 256>>>(x);

    reduce_kernel<<<(BATCH * DIM / 4) / 256, 256>>>();

    dim3 g3(BATCH / 128, NF / 128);
    gemm3_kernel<<<g3, 256>>>(bias, out);
}

// round 5
// speedup vs baseline: 2.1256x; 1.1562x over previous
#include <cuda_runtime.h>

#define BATCH 4096
#define NF    8192
#define DIM   256
#define HEADS 4
#define CELLS 32
#define SPLITK 16

// ---------------- scratch (device globals; no allocs allowed) ----------------
__device__ float g_reps[NF * DIM];                    // 8 MB
__device__ float g_part[SPLITK][BATCH * DIM];         // 64 MB
__device__ float g_hidden[BATCH * DIM];               // 4 MB

// ---------------- f32x2 helpers (packed FFMA2 path, PTX-only) ----------------
__device__ __forceinline__ unsigned long long pack2_dup(float v) {
    unsigned long long r;
    unsigned int u = __float_as_uint(v);
    asm("mov.b64 %0, {%1, %2};" : "=l"(r) : "r"(u), "r"(u));
    return r;
}
__device__ __forceinline__ void fma2(unsigned long long& d,
                                     unsigned long long a,
                                     unsigned long long b) {
    asm("fma.rn.f32x2 %0, %1, %2, %0;" : "+l"(d) : "l"(a), "l"(b));
}
__device__ __forceinline__ void unpack2(unsigned long long v, float& lo, float& hi) {
    unsigned int l, h;
    asm("mov.b64 {%0, %1}, %2;" : "=r"(l), "=r"(h) : "l"(v));
    lo = __uint_as_float(l);
    hi = __uint_as_float(h);
}

// 16-byte-chunk XOR swizzle (injective, stays within an 8-chunk group pair).
__device__ __forceinline__ int swc(int c) { return c ^ ((c >> 3) & 1); }

// =====================================================================
// Kernel 1: reps[n,:] = latent + sum_h gate-blended codebook rows
// Persistent: 148 blocks, rows strided. Router W (128KB) in dyn smem.
// =====================================================================
__global__ void reps_kernel(const float* __restrict__ proj,
                            const float* __restrict__ rw,
                            const float* __restrict__ rb,
                            const float* __restrict__ cb) {
    extern __shared__ float Wsh[];              // HEADS*CELLS*DIM floats
    __shared__ float lat[DIM];
    __shared__ float sc[HEADS * CELLS];
    __shared__ float g_sh[HEADS];
    __shared__ int   w_sh[HEADS];
    __shared__ int   r_sh[HEADS];

    const int tid  = threadIdx.x;
    const int lane = tid & 31;
    const int warp = tid >> 5;

    for (int i = tid; i < HEADS * CELLS * DIM; i += 256)
        Wsh[i] = rw[i];
    __syncthreads();

    for (int row = blockIdx.x; row < NF; row += gridDim.x) {
        lat[tid] = proj[row * DIM + tid];
        __syncthreads();

        float la[8];
        #pragma unroll
        for (int i = 0; i < 8; ++i) la[i] = lat[lane + 32 * i];

        #pragma unroll 1
        for (int pi = 0; pi < 16; ++pi) {
            const int p = warp * 16 + pi;
            const float* wrow = &Wsh[p * DIM];
            float m = -3.4e38f;
            #pragma unroll
            for (int i = 0; i < 8; ++i)
                m = fmaxf(m, la[i] + wrow[lane + 32 * i]);
            #pragma unroll
            for (int off = 16; off >= 1; off >>= 1)
                m = fmaxf(m, __shfl_xor_sync(0xffffffffu, m, off));
            if (lane == 0) sc[p] = m + rb[p];
        }
        __syncthreads();

        if (warp < HEADS) {
            const float s = sc[warp * CELLS + lane];
            float v = s; int idx = lane;
            #pragma unroll
            for (int off = 16; off >= 1; off >>= 1) {
                float ov = __shfl_xor_sync(0xffffffffu, v, off);
                int   oi = __shfl_xor_sync(0xffffffffu, idx, off);
                if (ov > v || (ov == v && oi < idx)) { v = ov; idx = oi; }
            }
            const float v1 = v; const int i1 = idx;
            v = (lane == i1) ? -3.4e38f : s; idx = lane;
            #pragma unroll
            for (int off = 16; off >= 1; off >>= 1) {
                float ov = __shfl_xor_sync(0xffffffffu, v, off);
                int   oi = __shfl_xor_sync(0xffffffffu, idx, off);
                if (ov > v || (ov == v && oi < idx)) { v = ov; idx = oi; }
            }
            if (lane == 0) {
                g_sh[warp] = 1.0f / (1.0f + expf(-(v1 - v)));
                w_sh[warp] = i1;
                r_sh[warp] = idx;
            }
        }
        __syncthreads();

        float acc = lat[tid];
        #pragma unroll
        for (int h = 0; h < HEADS; ++h) {
            const float g = g_sh[h];
            acc += g          * cb[(h * CELLS + w_sh[h]) * DIM + tid]
                 + (1.0f - g) * cb[(h * CELLS + r_sh[h]) * DIM + tid];
        }
        g_reps[row * DIM + tid] = acc;
        __syncthreads();
    }
}

// =====================================================================
// Shared GEMM geometry: BM=128 BN=256 BK=8, 256 thr, 1 CTA/SM.
// Warps 2(M)x4(N) -> warp tile 64x64. Thread 8M x 16N (8 f32x2 N-pairs).
// acc[i][j] = f32x2 (C[m_i][2j], C[m_i][2j+1]); A dup'd in regs, B natural.
// =====================================================================

// Kernel 2: partial[bz] = X[:, kchunk] @ reps[kchunk, :]   (split-K=16)
__global__ void __launch_bounds__(256, 1) gemm2_kernel(const float* __restrict__ X) {
    const int KC = NF / SPLITK;                 // 512
    const int bm = blockIdx.x, bz = blockIdx.z;
    const int k0 = bz * KC;
    const int tid = threadIdx.x;
    const int lane = tid & 31, warp = tid >> 5;
    const int warp_m = warp & 1, warp_n = warp >> 1;
    const int lane_m = lane >> 2, lane_n = lane & 3;

    __shared__ __align__(16) float As[2][8][128];
    __shared__ __align__(16) float Bs[2][8][256];

    unsigned long long acc[8][8];
    #pragma unroll
    for (int i = 0; i < 8; ++i)
        #pragma unroll
        for (int j = 0; j < 8; ++j) acc[i][j] = 0ull;

    const float* Xb = X + (size_t)(bm * 128) * NF + k0;
    const float* Rb = g_reps + (size_t)k0 * DIM;

    // global -> smem mapping
    const int ar = tid >> 1;                 // 0..127 M row
    const int ac = (tid & 1) * 4;            // k offset 0/4
    const int ars = (swc(ar >> 2) << 2) | (ar & 3);
    const int br = tid >> 5;                 // 0..7 k row
    const int bc1 = tid & 31;                // chunk (float4) index
    const int bc2 = bc1 + 32;
    const int bs1 = swc(bc1) << 2;
    const int bs2 = swc(bc2) << 2;

    // fragment read bases (swizzled)
    const int am0 = warp_m * 64 + lane_m * 8;
    const int aC0 = swc(am0 >> 2) << 2;
    const int aC1 = swc((am0 >> 2) + 1) << 2;
    const int n0 = warp_n * 64 + lane_n * 16;
    const int cB = n0 >> 2;
    const int bC0 = swc(cB + 0) << 2;
    const int bC1 = swc(cB + 1) << 2;
    const int bC2 = swc(cB + 2) << 2;
    const int bC3 = swc(cB + 3) << 2;

    // preload tile 0
    {
        float4 a0 = *(const float4*)&Xb[(size_t)ar * NF + ac];
        float4 b1 = *(const float4*)&Rb[br * DIM + bc1 * 4];
        float4 b2 = *(const float4*)&Rb[br * DIM + bc2 * 4];
        #pragma unroll
        for (int j = 0; j < 4; ++j) As[0][ac + j][ars] = ((const float*)&a0)[j];
        *(float4*)&Bs[0][br][bs1] = b1;
        *(float4*)&Bs[0][br][bs2] = b2;
    }
    __syncthreads();

    const int NT = KC / 8;                   // 64
    for (int t = 0; t < NT; ++t) {
        const int cur = t & 1, nxt = cur ^ 1;
        float4 na, nb1, nb2;
        if (t + 1 < NT) {
            na  = *(const float4*)&Xb[(size_t)ar * NF + (t + 1) * 8 + ac];
            nb1 = *(const float4*)&Rb[((t + 1) * 8 + br) * DIM + bc1 * 4];
            nb2 = *(const float4*)&Rb[((t + 1) * 8 + br) * DIM + bc2 * 4];
        }
        #pragma unroll
        for (int k = 0; k < 8; ++k) {
            float4 av0 = *(const float4*)&As[cur][k][aC0];
            float4 av1 = *(const float4*)&As[cur][k][aC1];
            unsigned long long ad[8];
            ad[0] = pack2_dup(av0.x); ad[1] = pack2_dup(av0.y);
            ad[2] = pack2_dup(av0.z); ad[3] = pack2_dup(av0.w);
            ad[4] = pack2_dup(av1.x); ad[5] = pack2_dup(av1.y);
            ad[6] = pack2_dup(av1.z); ad[7] = pack2_dup(av1.w);
            ulonglong2 b01 = *(const ulonglong2*)&Bs[cur][k][bC0];
            ulonglong2 b23 = *(const ulonglong2*)&Bs[cur][k][bC1];
            ulonglong2 b45 = *(const ulonglong2*)&Bs[cur][k][bC2];
            ulonglong2 b67 = *(const ulonglong2*)&Bs[cur][k][bC3];
            unsigned long long bp[8] = {b01.x, b01.y, b23.x, b23.y,
                                        b45.x, b45.y, b67.x, b67.y};
            #pragma unroll
            for (int i = 0; i < 8; ++i)
                #pragma unroll
                for (int j = 0; j < 8; ++j) fma2(acc[i][j], ad[i], bp[j]);
        }
        if (t + 1 < NT) {
            #pragma unroll
            for (int j = 0; j < 4; ++j) As[nxt][ac + j][ars] = ((const float*)&na)[j];
            *(float4*)&Bs[nxt][br][bs1] = nb1;
            *(float4*)&Bs[nxt][br][bs2] = nb2;
        }
        __syncthreads();
    }

    float* P = g_part[bz];
    const int m0 = bm * 128 + am0;
    #pragma unroll
    for (int i = 0; i < 8; ++i) {
        float lo[8], hi[8];
        #pragma unroll
        for (int j = 0; j < 8; ++j) unpack2(acc[i][j], lo[j], hi[j]);
        float* r = &P[(m0 + i) * DIM + n0];
        *(float4*)&r[0]  = make_float4(lo[0], hi[0], lo[1], hi[1]);
        *(float4*)&r[4]  = make_float4(lo[2], hi[2], lo[3], hi[3]);
        *(float4*)&r[8]  = make_float4(lo[4], hi[4], lo[5], hi[5]);
        *(float4*)&r[12] = make_float4(lo[6], hi[6], lo[7], hi[7]);
    }
}

// deterministic split-K reduction (16-way)
__global__ void reduce_kernel() {
    const int i = blockIdx.x * 256 + threadIdx.x;   // float4 index
    float4 s = ((const float4*)g_part[0])[i];
    #pragma unroll
    for (int z = 1; z < SPLITK; ++z) {
        float4 p = ((const float4*)g_part[z])[i];
        s.x += p.x; s.y += p.y; s.z += p.z; s.w += p.w;
    }
    ((float4*)g_hidden)[i] = s;
}

// Kernel 3: out = relu(hidden @ reps^T + bias)
__global__ void __launch_bounds__(256, 1) gemm3_kernel(const float* __restrict__ bias,
                                                       float* __restrict__ out) {
    const int bm = blockIdx.x, bn = blockIdx.y;
    const int tid = threadIdx.x;
    const int lane = tid & 31, warp = tid >> 5;
    const int warp_m = warp & 1, warp_n = warp >> 1;
    const int lane_m = lane >> 2, lane_n = lane & 3;

    __shared__ __align__(16) float As[2][8][128];
    __shared__ __align__(16) float Bs[2][8][256];

    unsigned long long acc[8][8];
    #pragma unroll
    for (int i = 0; i < 8; ++i)
        #pragma unroll
        for (int j = 0; j < 8; ++j) acc[i][j] = 0ull;

    const float* Ab = g_hidden + (size_t)(bm * 128) * DIM;
    const float* Rb = g_reps + (size_t)(bn * 256) * DIM;

    // A: thread loads hidden[ar][kt+ac..+3], scalar-stores to As[k][m]
    const int ar = tid >> 1;
    const int ac = (tid & 1) * 4;
    const int ars = (swc(ar >> 2) << 2) | (ar & 3);
    // B: thread t owns n = t; loads reps[n][kt..kt+7]; scalar-stores Bs[k][n]
    const int bn_l = tid;                    // 0..255
    const int bns = (swc(bn_l >> 2) << 2) | (bn_l & 3);

    const int am0 = warp_m * 64 + lane_m * 8;
    const int aC0 = swc(am0 >> 2) << 2;
    const int aC1 = swc((am0 >> 2) + 1) << 2;
    const int n0 = warp_n * 64 + lane_n * 16;
    const int cB = n0 >> 2;
    const int bC0 = swc(cB + 0) << 2;
    const int bC1 = swc(cB + 1) << 2;
    const int bC2 = swc(cB + 2) << 2;
    const int bC3 = swc(cB + 3) << 2;

    {
        float4 a0 = *(const float4*)&Ab[ar * DIM + ac];
        float4 b0 = *(const float4*)&Rb[bn_l * DIM + 0];
        float4 b1 = *(const float4*)&Rb[bn_l * DIM + 4];
        #pragma unroll
        for (int j = 0; j < 4; ++j) {
            As[0][ac + j][ars] = ((const float*)&a0)[j];
            Bs[0][j][bns]     = ((const float*)&b0)[j];
            Bs[0][4 + j][bns] = ((const float*)&b1)[j];
        }
    }
    __syncthreads();

    const int NT = DIM / 8;                  // 32
    for (int t = 0; t < NT; ++t) {
        const int cur = t & 1, nxt = cur ^ 1;
        float4 na, nb0, nb1;
        if (t + 1 < NT) {
            na  = *(const float4*)&Ab[ar * DIM + (t + 1) * 8 + ac];
            nb0 = *(const float4*)&Rb[bn_l * DIM + (t + 1) * 8];
            nb1 = *(const float4*)&Rb[bn_l * DIM + (t + 1) * 8 + 4];
        }
        #pragma unroll
        for (int k = 0; k < 8; ++k) {
            float4 av0 = *(const float4*)&As[cur][k][aC0];
            float4 av1 = *(const float4*)&As[cur][k][aC1];
            unsigned long long ad[8];
            ad[0] = pack2_dup(av0.x); ad[1] = pack2_dup(av0.y);
            ad[2] = pack2_dup(av0.z); ad[3] = pack2_dup(av0.w);
            ad[4] = pack2_dup(av1.x); ad[5] = pack2_dup(av1.y);
            ad[6] = pack2_dup(av1.z); ad[7] = pack2_dup(av1.w);
            ulonglong2 b01 = *(const ulonglong2*)&Bs[cur][k][bC0];
            ulonglong2 b23 = *(const ulonglong2*)&Bs[cur][k][bC1];
            ulonglong2 b45 = *(const ulonglong2*)&Bs[cur][k][bC2];
            ulonglong2 b67 = *(const ulonglong2*)&Bs[cur][k][bC3];
            unsigned long long bp[8] = {b01.x, b01.y, b23.x, b23.y,
                                        b45.x, b45.y, b67.x, b67.y};
            #pragma unroll
            for (int i = 0; i < 8; ++i)
                #pragma unroll
                for (int j = 0; j < 8; ++j) fma2(acc[i][j], ad[i], bp[j]);
        }
        if (t + 1 < NT) {
            #pragma unroll
            for (int j = 0; j < 4; ++j) {
                As[nxt][ac + j][ars] = ((const float*)&na)[j];
                Bs[nxt][j][bns]     = ((const float*)&nb0)[j];
                Bs[nxt][4 + j][bns] = ((const float*)&nb1)[j];
            }
        }
        __syncthreads();
    }

    const int m0 = bm * 128 + am0;
    const int n0g = bn * 256 + n0;
    float bi[16];
    *(float4*)&bi[0]  = *(const float4*)&bias[n0g];
    *(float4*)&bi[4]  = *(const float4*)&bias[n0g + 4];
    *(float4*)&bi[8]  = *(const float4*)&bias[n0g + 8];
    *(float4*)&bi[12] = *(const float4*)&bias[n0g + 12];

    #pragma unroll
    for (int i = 0; i < 8; ++i) {
        float v[16];
        #pragma unroll
        for (int j = 0; j < 8; ++j) {
            float lo, hi;
            unpack2(acc[i][j], lo, hi);
            v[2 * j]     = fmaxf(lo + bi[2 * j], 0.0f);
            v[2 * j + 1] = fmaxf(hi + bi[2 * j + 1], 0.0f);
        }
        float* r = &out[(size_t)(m0 + i) * NF + n0g];
        *(float4*)&r[0]  = *(float4*)&v[0];
        *(float4*)&r[4]  = *(float4*)&v[4];
        *(float4*)&r[8]  = *(float4*)&v[8];
        *(float4*)&r[12] = *(float4*)&v[12];
    }
}

// =====================================================================
extern "C" void kernel_launch(void* const* d_in, const int* in_sizes, int n_in,
                              void* d_out, int out_size) {
    const float* x    = (const float*)d_in[0];
    const float* proj = (const float*)d_in[1];
    const float* rw   = (const float*)d_in[2];
    const float* rb   = (const float*)d_in[3];
    const float* cb   = (const float*)d_in[4];
    const float* bias = (const float*)d_in[5];
    float* out = (float*)d_out;

    const int wbytes = HEADS * CELLS * DIM * (int)sizeof(float);   // 128 KB
    cudaFuncSetAttribute((const void*)reps_kernel,
                         cudaFuncAttributeMaxDynamicSharedMemorySize, wbytes);
    reps_kernel<<<148, 256, wbytes>>>(proj, rw, rb, cb);

    dim3 g2(BATCH / 128, 1, SPLITK);
    gemm2_kernel<<<g2, 256>>>(x);

    reduce_kernel<<<(BATCH * DIM / 4) / 256, 256>>>();

    dim3 g3(BATCH / 128, NF / 256);
    gemm3_kernel<<<g3, 256>>>(bias, out);
}

// round 7
// speedup vs baseline: 3.6181x; 1.7022x over previous
#include <cuda_runtime.h>
#include <cuda_bf16.h>
#include <cstdint>

#define BATCH 4096
#define NF    8192
#define DIM   256
#define HEADS 4
#define CELLS 32
#define SK2   4            // gemm2 split-K

// ---------------- scratch (device globals; no allocs allowed) ----------------
__device__ __align__(16) __nv_bfloat16 g_xhi[(size_t)BATCH * NF];
__device__ __align__(16) __nv_bfloat16 g_xlo[(size_t)BATCH * NF];
__device__ float g_reps[NF * DIM];
__device__ __align__(16) __nv_bfloat16 g_bhi[NF * DIM];    // reps   [NF][DIM]
__device__ __align__(16) __nv_bfloat16 g_blo[NF * DIM];
__device__ __align__(16) __nv_bfloat16 g_bthi[DIM * NF];   // reps^T [DIM][NF]
__device__ __align__(16) __nv_bfloat16 g_btlo[DIM * NF];
__device__ float g_part[SK2][(size_t)BATCH * DIM];
__device__ __align__(16) __nv_bfloat16 g_ahi[BATCH * DIM];
__device__ __align__(16) __nv_bfloat16 g_alo[BATCH * DIM];

// ---------------- PTX helpers (base ISA only, no 'a' features) ----------------
__device__ __forceinline__ uint32_t smem_u32(const void* p) {
    uint32_t a;
    asm("{ .reg .u64 t; cvta.to.shared.u64 t, %1; cvt.u32.u64 %0, t; }" : "=r"(a) : "l"(p));
    return a;
}
__device__ __forceinline__ void cp16(uint32_t d, const void* s) {
    asm volatile("cp.async.cg.shared.global [%0], [%1], 16;" :: "r"(d), "l"(s));
}
__device__ __forceinline__ void cp_commit() {
    asm volatile("cp.async.commit_group;" ::: "memory");
}
__device__ __forceinline__ void cp_wait0() {
    asm volatile("cp.async.wait_group 0;" ::: "memory");
}
__device__ __forceinline__ void cp_wait1() {
    asm volatile("cp.async.wait_group 1;" ::: "memory");
}
__device__ __forceinline__ void ldsm4(uint32_t& r0, uint32_t& r1, uint32_t& r2,
                                      uint32_t& r3, uint32_t a) {
    asm volatile("ldmatrix.sync.aligned.m8n8.x4.shared.b16 {%0,%1,%2,%3}, [%4];"
                 : "=r"(r0), "=r"(r1), "=r"(r2), "=r"(r3) : "r"(a));
}
__device__ __forceinline__ void mma16816(float* d, const uint32_t* a,
                                         uint32_t b0, uint32_t b1) {
    asm volatile(
        "mma.sync.aligned.m16n8k16.row.col.f32.bf16.bf16.f32 "
        "{%0,%1,%2,%3}, {%4,%5,%6,%7}, {%8,%9}, {%0,%1,%2,%3};"
        : "+f"(d[0]), "+f"(d[1]), "+f"(d[2]), "+f"(d[3])
        : "r"(a[0]), "r"(a[1]), "r"(a[2]), "r"(a[3]), "r"(b0), "r"(b1));
}

// smem tile layout: 128 rows x 32 bf16 (= 4 16B chunks/row), chunk swizzle
// phys_chunk = c ^ ((r>>1)&3)  -> conflict-free for stores and ldmatrix.
#define OFF_AH 0
#define OFF_AL 8192
#define OFF_BH 16384
#define OFF_BL 24576
#define BUF_STRIDE 32768
#define GEMM_SMEM (2 * BUF_STRIDE)    // 64 KB

__device__ __forceinline__ uint32_t tswz(int r, int c) {
    return (uint32_t)(r * 64 + ((c ^ ((r >> 1) & 3)) << 4));
}

// =====================================================================
// Kernel 1: reps (proven)
// =====================================================================
__global__ void reps_kernel(const float* __restrict__ proj,
                            const float* __restrict__ rw,
                            const float* __restrict__ rb,
                            const float* __restrict__ cb) {
    extern __shared__ float Wsh[];
    __shared__ float lat[DIM];
    __shared__ float sc[HEADS * CELLS];
    __shared__ float g_sh[HEADS];
    __shared__ int   w_sh[HEADS];
    __shared__ int   r_sh[HEADS];

    const int tid  = threadIdx.x;
    const int lane = tid & 31;
    const int warp = tid >> 5;

    for (int i = tid; i < HEADS * CELLS * DIM; i += 256)
        Wsh[i] = rw[i];
    __syncthreads();

    for (int row = blockIdx.x; row < NF; row += gridDim.x) {
        lat[tid] = proj[row * DIM + tid];
        __syncthreads();

        float la[8];
        #pragma unroll
        for (int i = 0; i < 8; ++i) la[i] = lat[lane + 32 * i];

        #pragma unroll 1
        for (int pi = 0; pi < 16; ++pi) {
            const int p = warp * 16 + pi;
            const float* wrow = &Wsh[p * DIM];
            float m = -3.4e38f;
            #pragma unroll
            for (int i = 0; i < 8; ++i)
                m = fmaxf(m, la[i] + wrow[lane + 32 * i]);
            #pragma unroll
            for (int off = 16; off >= 1; off >>= 1)
                m = fmaxf(m, __shfl_xor_sync(0xffffffffu, m, off));
            if (lane == 0) sc[p] = m + rb[p];
        }
        __syncthreads();

        if (warp < HEADS) {
            const float s = sc[warp * CELLS + lane];
            float v = s; int idx = lane;
            #pragma unroll
            for (int off = 16; off >= 1; off >>= 1) {
                float ov = __shfl_xor_sync(0xffffffffu, v, off);
                int   oi = __shfl_xor_sync(0xffffffffu, idx, off);
                if (ov > v || (ov == v && oi < idx)) { v = ov; idx = oi; }
            }
            const float v1 = v; const int i1 = idx;
            v = (lane == i1) ? -3.4e38f : s; idx = lane;
            #pragma unroll
            for (int off = 16; off >= 1; off >>= 1) {
                float ov = __shfl_xor_sync(0xffffffffu, v, off);
                int   oi = __shfl_xor_sync(0xffffffffu, idx, off);
                if (ov > v || (ov == v && oi < idx)) { v = ov; idx = oi; }
            }
            if (lane == 0) {
                g_sh[warp] = 1.0f / (1.0f + expf(-(v1 - v)));
                w_sh[warp] = i1;
                r_sh[warp] = idx;
            }
        }
        __syncthreads();

        float acc = lat[tid];
        #pragma unroll
        for (int h = 0; h < HEADS; ++h) {
            const float g = g_sh[h];
            acc += g          * cb[(h * CELLS + w_sh[h]) * DIM + tid]
                 + (1.0f - g) * cb[(h * CELLS + r_sh[h]) * DIM + tid];
        }
        g_reps[row * DIM + tid] = acc;
        __syncthreads();
    }
}

// =====================================================================
// Kernel 2: x -> bf16 hi/lo
// =====================================================================
__global__ void cvtx_kernel(const float* __restrict__ x) {
    const size_t i = ((size_t)blockIdx.x * 256 + threadIdx.x) * 4;
    float4 v = *(const float4*)(x + i);
    __nv_bfloat16 h0 = __float2bfloat16_rn(v.x);
    __nv_bfloat16 h1 = __float2bfloat16_rn(v.y);
    __nv_bfloat16 h2 = __float2bfloat16_rn(v.z);
    __nv_bfloat16 h3 = __float2bfloat16_rn(v.w);
    __nv_bfloat16 l0 = __float2bfloat16_rn(v.x - __bfloat162float(h0));
    __nv_bfloat16 l1 = __float2bfloat16_rn(v.y - __bfloat162float(h1));
    __nv_bfloat16 l2 = __float2bfloat16_rn(v.z - __bfloat162float(h2));
    __nv_bfloat16 l3 = __float2bfloat16_rn(v.w - __bfloat162float(h3));
    *(__nv_bfloat162*)&g_xhi[i]     = __halves2bfloat162(h0, h1);
    *(__nv_bfloat162*)&g_xhi[i + 2] = __halves2bfloat162(h2, h3);
    *(__nv_bfloat162*)&g_xlo[i]     = __halves2bfloat162(l0, l1);
    *(__nv_bfloat162*)&g_xlo[i + 2] = __halves2bfloat162(l2, l3);
}

// =====================================================================
// Kernel 3: reps -> bf16 hi/lo + transposed hi/lo
// =====================================================================
__global__ void trans_kernel() {
    __shared__ float tile[32][33];
    const int r0 = blockIdx.x * 32;     // NF dim
    const int c0 = blockIdx.y * 32;     // DIM dim
    const int tid = threadIdx.x;
    #pragma unroll
    for (int i = 0; i < 4; ++i) {
        const int idx = tid + i * 256;
        const int rr = idx >> 5, cc = idx & 31;
        const float v = g_reps[(r0 + rr) * DIM + c0 + cc];
        tile[rr][cc] = v;
        __nv_bfloat16 h = __float2bfloat16_rn(v);
        g_bhi[(r0 + rr) * DIM + c0 + cc] = h;
        g_blo[(r0 + rr) * DIM + c0 + cc] =
            __float2bfloat16_rn(v - __bfloat162float(h));
    }
    __syncthreads();
    #pragma unroll
    for (int i = 0; i < 4; ++i) {
        const int idx = tid + i * 256;
        const int rr = idx >> 5, cc = idx & 31;
        const float v = tile[cc][rr];
        __nv_bfloat16 h = __float2bfloat16_rn(v);
        g_bthi[(size_t)(c0 + rr) * NF + r0 + cc] = h;
        g_btlo[(size_t)(c0 + rr) * NF + r0 + cc] =
            __float2bfloat16_rn(v - __bfloat162float(h));
    }
}

// =====================================================================
// Tile copy: A/B each 128 rows x 32 bf16, hi+lo, swizzled. One commit group.
// =====================================================================
__device__ __forceinline__ void copy_tiles(
    uint32_t base, int tid,
    const __nv_bfloat16* Ah, const __nv_bfloat16* Al, size_t ap,
    const __nv_bfloat16* Bh, const __nv_bfloat16* Bl, size_t bp) {
    #pragma unroll
    for (int p = 0; p < 2; ++p) {
        const int idx = tid + p * 256;       // 512 chunks
        const int r = idx >> 2, c = idx & 3;
        const uint32_t off = tswz(r, c);
        const size_t g = (size_t)r;
        cp16(base + OFF_AH + off, Ah + g * ap + c * 8);
        cp16(base + OFF_AL + off, Al + g * ap + c * 8);
        cp16(base + OFF_BH + off, Bh + g * bp + c * 8);
        cp16(base + OFF_BL + off, Bl + g * bp + c * 8);
    }
    cp_commit();
}

// =====================================================================
// mainloop macro: BM=128 BN=128 BK=32, 8 warps (2Mx4N), warp tile 64x32,
// bf16 3-split (AhBh + AhBl + AlBh), fp32 acc[4][4][4].
// =====================================================================
#define GEMM_MAINLOOP(sb, tid, Ah, Al, AP, Bh, Bl, BP, NT, acc)                       \
{                                                                                     \
    const int lane = (tid) & 31, warp = (tid) >> 5;                                   \
    const int wm = warp & 1, wn = warp >> 1;                                          \
    const int rsub = lane & 15, csub = lane >> 4;                                     \
    int arow[4], brow[2];                                                             \
    _Pragma("unroll") for (int i = 0; i < 4; ++i) arow[i] = wm * 64 + i * 16 + rsub;  \
    _Pragma("unroll") for (int j = 0; j < 2; ++j) brow[j] = wn * 32 + j * 16 + rsub;  \
    copy_tiles((sb), (tid), (Ah), (Al), (AP), (Bh), (Bl), (BP));                      \
    for (int t = 0; t < (NT); ++t) {                                                  \
        const uint32_t cb_ = (sb) + (uint32_t)(t & 1) * BUF_STRIDE;                   \
        if (t + 1 < (NT)) {                                                           \
            const int kc = (t + 1) * 32;                                              \
            copy_tiles((sb) + (uint32_t)((t + 1) & 1) * BUF_STRIDE, (tid),            \
                       (Ah) + kc, (Al) + kc, (AP), (Bh) + kc, (Bl) + kc, (BP));       \
            cp_wait1();                                                               \
        } else {                                                                      \
            cp_wait0();                                                               \
        }                                                                             \
        __syncthreads();                                                              \
        _Pragma("unroll") for (int h = 0; h < 2; ++h) {                               \
            uint32_t ah[4][4], al[4][4], bh[2][4], bl[2][4];                          \
            _Pragma("unroll") for (int i = 0; i < 4; ++i) {                           \
                const uint32_t ao = tswz(arow[i], 2 * h + csub);                      \
                ldsm4(ah[i][0], ah[i][1], ah[i][2], ah[i][3], cb_ + OFF_AH + ao);     \
                ldsm4(al[i][0], al[i][1], al[i][2], al[i][3], cb_ + OFF_AL + ao);     \
            }                                                                         \
            _Pragma("unroll") for (int j = 0; j < 2; ++j) {                           \
                const uint32_t bo = tswz(brow[j], 2 * h + csub);                      \
                ldsm4(bh[j][0], bh[j][1], bh[j][2], bh[j][3], cb_ + OFF_BH + bo);     \
                ldsm4(bl[j][0], bl[j][1], bl[j][2], bl[j][3], cb_ + OFF_BL + bo);     \
            }                                                                         \
            _Pragma("unroll") for (int i = 0; i < 4; ++i)                             \
            _Pragma("unroll") for (int j2 = 0; j2 < 2; ++j2)                          \
            _Pragma("unroll") for (int s = 0; s < 2; ++s) {                           \
                float* d = acc[i][j2 * 2 + s];                                        \
                mma16816(d, ah[i], bh[j2][s], bh[j2][s + 2]);                         \
                mma16816(d, ah[i], bl[j2][s], bl[j2][s + 2]);                         \
                mma16816(d, al[i], bh[j2][s], bh[j2][s + 2]);                         \
            }                                                                         \
        }                                                                             \
        __syncthreads();                                                              \
    }                                                                                 \
}

// =====================================================================
// Kernel 4: gemm2: partial[bz] = X[:,kslice] @ reps[kslice,:]  (split-K=4)
// =====================================================================
__global__ void __launch_bounds__(256, 1) gemm2_mm(void) {
    extern __shared__ char smem[];
    const uint32_t sb = smem_u32(smem);
    const int tid = threadIdx.x;
    const int bm = blockIdx.x, bn = blockIdx.y, bz = blockIdx.z;
    const int k0 = bz * (NF / SK2);
    const int NT = (NF / SK2) / 32;         // 64

    float acc[4][4][4];
    #pragma unroll
    for (int i = 0; i < 4; ++i)
        #pragma unroll
        for (int j = 0; j < 4; ++j)
            #pragma unroll
            for (int s = 0; s < 4; ++s) acc[i][j][s] = 0.0f;

    const __nv_bfloat16* Ah = g_xhi + (size_t)(bm * 128) * NF + k0;
    const __nv_bfloat16* Al = g_xlo + (size_t)(bm * 128) * NF + k0;
    const __nv_bfloat16* Bh = g_bthi + (size_t)(bn * 128) * NF + k0;
    const __nv_bfloat16* Bl = g_btlo + (size_t)(bn * 128) * NF + k0;

    GEMM_MAINLOOP(sb, tid, Ah, Al, NF, Bh, Bl, NF, NT, acc);

    const int lane = tid & 31, warp = tid >> 5;
    const int wm = warp & 1, wn = warp >> 1;
    float* P = g_part[bz];
    const int l4 = lane >> 2, l2 = (lane & 3) * 2;
    #pragma unroll
    for (int i = 0; i < 4; ++i) {
        const int r0 = bm * 128 + wm * 64 + i * 16 + l4;
        #pragma unroll
        for (int j = 0; j < 4; ++j) {
            const int n = bn * 128 + wn * 32 + j * 8 + l2;
            *(float2*)&P[(size_t)r0 * DIM + n]       = make_float2(acc[i][j][0], acc[i][j][1]);
            *(float2*)&P[(size_t)(r0 + 8) * DIM + n] = make_float2(acc[i][j][2], acc[i][j][3]);
        }
    }
}

// =====================================================================
// Kernel 5: sum split-K partials -> hidden bf16 hi/lo
// =====================================================================
__global__ void hconv_kernel() {
    const size_t i = ((size_t)blockIdx.x * 256 + threadIdx.x) * 4;
    float4 s = *(const float4*)&g_part[0][i];
    #pragma unroll
    for (int z = 1; z < SK2; ++z) {
        float4 p = *(const float4*)&g_part[z][i];
        s.x += p.x; s.y += p.y; s.z += p.z; s.w += p.w;
    }
    __nv_bfloat16 h0 = __float2bfloat16_rn(s.x);
    __nv_bfloat16 h1 = __float2bfloat16_rn(s.y);
    __nv_bfloat16 h2 = __float2bfloat16_rn(s.z);
    __nv_bfloat16 h3 = __float2bfloat16_rn(s.w);
    __nv_bfloat16 l0 = __float2bfloat16_rn(s.x - __bfloat162float(h0));
    __nv_bfloat16 l1 = __float2bfloat16_rn(s.y - __bfloat162float(h1));
    __nv_bfloat16 l2 = __float2bfloat16_rn(s.z - __bfloat162float(h2));
    __nv_bfloat16 l3 = __float2bfloat16_rn(s.w - __bfloat162float(h3));
    *(__nv_bfloat162*)&g_ahi[i]     = __halves2bfloat162(h0, h1);
    *(__nv_bfloat162*)&g_ahi[i + 2] = __halves2bfloat162(h2, h3);
    *(__nv_bfloat162*)&g_alo[i]     = __halves2bfloat162(l0, l1);
    *(__nv_bfloat162*)&g_alo[i + 2] = __halves2bfloat162(l2, l3);
}

// =====================================================================
// Kernel 6: gemm3: out = relu(hidden @ reps^T + bias)
// =====================================================================
__global__ void __launch_bounds__(256, 1) gemm3_mm(const float* __restrict__ bias,
                                                   float* __restrict__ out) {
    extern __shared__ char smem[];
    const uint32_t sb = smem_u32(smem);
    const int tid = threadIdx.x;
    const int bm = blockIdx.x, bn = blockIdx.y;
    const int NT = DIM / 32;                // 8

    float acc[4][4][4];
    #pragma unroll
    for (int i = 0; i < 4; ++i)
        #pragma unroll
        for (int j = 0; j < 4; ++j)
            #pragma unroll
            for (int s = 0; s < 4; ++s) acc[i][j][s] = 0.0f;

    const __nv_bfloat16* Ah = g_ahi + (size_t)(bm * 128) * DIM;
    const __nv_bfloat16* Al = g_alo + (size_t)(bm * 128) * DIM;
    const __nv_bfloat16* Bh = g_bhi + (size_t)(bn * 128) * DIM;
    const __nv_bfloat16* Bl = g_blo + (size_t)(bn * 128) * DIM;

    GEMM_MAINLOOP(sb, tid, Ah, Al, DIM, Bh, Bl, DIM, NT, acc);

    const int lane = tid & 31, warp = tid >> 5;
    const int wm = warp & 1, wn = warp >> 1;
    const int l4 = lane >> 2, l2 = (lane & 3) * 2;
    #pragma unroll
    for (int i = 0; i < 4; ++i) {
        const int r0 = bm * 128 + wm * 64 + i * 16 + l4;
        #pragma unroll
        for (int j = 0; j < 4; ++j) {
            const int n = bn * 128 + wn * 32 + j * 8 + l2;
            const float b0 = bias[n], b1 = bias[n + 1];
            float2 v0 = make_float2(fmaxf(acc[i][j][0] + b0, 0.0f),
                                    fmaxf(acc[i][j][1] + b1, 0.0f));
            float2 v1 = make_float2(fmaxf(acc[i][j][2] + b0, 0.0f),
                                    fmaxf(acc[i][j][3] + b1, 0.0f));
            *(float2*)&out[(size_t)r0 * NF + n]       = v0;
            *(float2*)&out[(size_t)(r0 + 8) * NF + n] = v1;
        }
    }
}

// =====================================================================
extern "C" void kernel_launch(void* const* d_in, const int* in_sizes, int n_in,
                              void* d_out, int out_size) {
    const float* x    = (const float*)d_in[0];
    const float* proj = (const float*)d_in[1];
    const float* rw   = (const float*)d_in[2];
    const float* rb   = (const float*)d_in[3];
    const float* cb   = (const float*)d_in[4];
    const float* bias = (const float*)d_in[5];
    float* out = (float*)d_out;

    const int wbytes = HEADS * CELLS * DIM * (int)sizeof(float);   // 128 KB
    cudaFuncSetAttribute((const void*)reps_kernel,
                         cudaFuncAttributeMaxDynamicSharedMemorySize, wbytes);
    cudaFuncSetAttribute((const void*)gemm2_mm,
                         cudaFuncAttributeMaxDynamicSharedMemorySize, GEMM_SMEM);
    cudaFuncSetAttribute((const void*)gemm3_mm,
                         cudaFuncAttributeMaxDynamicSharedMemorySize, GEMM_SMEM);

    cvtx_kernel<<<(int)(((size_t)BATCH * NF / 4) / 256), 256>>>(x);
    reps_kernel<<<148, 256, wbytes>>>(proj, rw, rb, cb);
    trans_kernel<<<dim3(NF / 32, DIM / 32), 256>>>();

    gemm2_mm<<<dim3(BATCH / 128, DIM / 128, SK2), 256, GEMM_SMEM>>>();
    hconv_kernel<<<(BATCH * DIM / 4) / 256, 256>>>();
    gemm3_mm<<<dim3(BATCH / 128, NF / 128), 256, GEMM_SMEM>>>(bias, out);
}

// round 8
// speedup vs baseline: 3.6760x; 1.0160x over previous
#include <cuda_runtime.h>
#include <cuda_bf16.h>
#include <cstdint>

#define BATCH 4096
#define NF    8192
#define DIM   256
#define HEADS 4
#define CELLS 32
#define SK2   4            // gemm2 split-K

// ---------------- scratch (device globals; no allocs allowed) ----------------
__device__ __align__(16) __nv_bfloat16 g_xhi[(size_t)BATCH * NF];
__device__ __align__(16) __nv_bfloat16 g_xlo[(size_t)BATCH * NF];
__device__ float g_reps[NF * DIM];
__device__ __align__(16) __nv_bfloat16 g_bhi[NF * DIM];    // reps   [NF][DIM]
__device__ __align__(16) __nv_bfloat16 g_blo[NF * DIM];
__device__ __align__(16) __nv_bfloat16 g_bthi[DIM * NF];   // reps^T [DIM][NF]
__device__ __align__(16) __nv_bfloat16 g_btlo[DIM * NF];
__device__ float g_part[SK2][(size_t)BATCH * DIM];
__device__ __align__(16) __nv_bfloat16 g_ahi[BATCH * DIM];
__device__ __align__(16) __nv_bfloat16 g_alo[BATCH * DIM];

// ---------------- PTX helpers (base ISA only) ----------------
__device__ __forceinline__ uint32_t smem_u32(const void* p) {
    uint32_t a;
    asm("{ .reg .u64 t; cvta.to.shared.u64 t, %1; cvt.u32.u64 %0, t; }" : "=r"(a) : "l"(p));
    return a;
}
__device__ __forceinline__ void cp16(uint32_t d, const void* s) {
    asm volatile("cp.async.cg.shared.global [%0], [%1], 16;" :: "r"(d), "l"(s));
}
__device__ __forceinline__ void cp_commit() {
    asm volatile("cp.async.commit_group;" ::: "memory");
}
__device__ __forceinline__ void cp_wait0() {
    asm volatile("cp.async.wait_group 0;" ::: "memory");
}
__device__ __forceinline__ void cp_wait1() {
    asm volatile("cp.async.wait_group 1;" ::: "memory");
}
__device__ __forceinline__ void ldsm4(uint32_t& r0, uint32_t& r1, uint32_t& r2,
                                      uint32_t& r3, uint32_t a) {
    asm volatile("ldmatrix.sync.aligned.m8n8.x4.shared.b16 {%0,%1,%2,%3}, [%4];"
                 : "=r"(r0), "=r"(r1), "=r"(r2), "=r"(r3) : "r"(a));
}
__device__ __forceinline__ void mma16816(float* d, const uint32_t* a,
                                         uint32_t b0, uint32_t b1) {
    asm volatile(
        "mma.sync.aligned.m16n8k16.row.col.f32.bf16.bf16.f32 "
        "{%0,%1,%2,%3}, {%4,%5,%6,%7}, {%8,%9}, {%0,%1,%2,%3};"
        : "+f"(d[0]), "+f"(d[1]), "+f"(d[2]), "+f"(d[3])
        : "r"(a[0]), "r"(a[1]), "r"(a[2]), "r"(a[3]), "r"(b0), "r"(b1));
}

// smem tile: 128 rows x 32 bf16 (4 16B chunks/row), chunk swizzle
// phys_chunk = c ^ ((r>>1)&3) -> conflict-free stores + ldmatrix.
#define OFF_AH 0
#define OFF_AL 8192
#define OFF_BH 16384
#define OFF_BL 24576
#define BUF_STRIDE 32768
#define N_STAGES 3
#define GEMM_SMEM (N_STAGES * BUF_STRIDE)    // 96 KB

__device__ __forceinline__ uint32_t tswz(int r, int c) {
    return (uint32_t)(r * 64 + ((c ^ ((r >> 1) & 3)) << 4));
}

// =====================================================================
// Kernel 1: reps (proven)
// =====================================================================
__global__ void reps_kernel(const float* __restrict__ proj,
                            const float* __restrict__ rw,
                            const float* __restrict__ rb,
                            const float* __restrict__ cb) {
    extern __shared__ float Wsh[];
    __shared__ float lat[DIM];
    __shared__ float sc[HEADS * CELLS];
    __shared__ float g_sh[HEADS];
    __shared__ int   w_sh[HEADS];
    __shared__ int   r_sh[HEADS];

    const int tid  = threadIdx.x;
    const int lane = tid & 31;
    const int warp = tid >> 5;

    for (int i = tid; i < HEADS * CELLS * DIM; i += 256)
        Wsh[i] = rw[i];
    __syncthreads();

    for (int row = blockIdx.x; row < NF; row += gridDim.x) {
        lat[tid] = proj[row * DIM + tid];
        __syncthreads();

        float la[8];
        #pragma unroll
        for (int i = 0; i < 8; ++i) la[i] = lat[lane + 32 * i];

        #pragma unroll 1
        for (int pi = 0; pi < 16; ++pi) {
            const int p = warp * 16 + pi;
            const float* wrow = &Wsh[p * DIM];
            float m = -3.4e38f;
            #pragma unroll
            for (int i = 0; i < 8; ++i)
                m = fmaxf(m, la[i] + wrow[lane + 32 * i]);
            #pragma unroll
            for (int off = 16; off >= 1; off >>= 1)
                m = fmaxf(m, __shfl_xor_sync(0xffffffffu, m, off));
            if (lane == 0) sc[p] = m + rb[p];
        }
        __syncthreads();

        if (warp < HEADS) {
            const float s = sc[warp * CELLS + lane];
            float v = s; int idx = lane;
            #pragma unroll
            for (int off = 16; off >= 1; off >>= 1) {
                float ov = __shfl_xor_sync(0xffffffffu, v, off);
                int   oi = __shfl_xor_sync(0xffffffffu, idx, off);
                if (ov > v || (ov == v && oi < idx)) { v = ov; idx = oi; }
            }
            const float v1 = v; const int i1 = idx;
            v = (lane == i1) ? -3.4e38f : s; idx = lane;
            #pragma unroll
            for (int off = 16; off >= 1; off >>= 1) {
                float ov = __shfl_xor_sync(0xffffffffu, v, off);
                int   oi = __shfl_xor_sync(0xffffffffu, idx, off);
                if (ov > v || (ov == v && oi < idx)) { v = ov; idx = oi; }
            }
            if (lane == 0) {
                g_sh[warp] = 1.0f / (1.0f + expf(-(v1 - v)));
                w_sh[warp] = i1;
                r_sh[warp] = idx;
            }
        }
        __syncthreads();

        float acc = lat[tid];
        #pragma unroll
        for (int h = 0; h < HEADS; ++h) {
            const float g = g_sh[h];
            acc += g          * cb[(h * CELLS + w_sh[h]) * DIM + tid]
                 + (1.0f - g) * cb[(h * CELLS + r_sh[h]) * DIM + tid];
        }
        g_reps[row * DIM + tid] = acc;
        __syncthreads();
    }
}

// =====================================================================
// Kernel 2: x -> bf16 hi/lo
// =====================================================================
__global__ void cvtx_kernel(const float* __restrict__ x) {
    const size_t i = ((size_t)blockIdx.x * 256 + threadIdx.x) * 4;
    float4 v = *(const float4*)(x + i);
    __nv_bfloat16 h0 = __float2bfloat16_rn(v.x);
    __nv_bfloat16 h1 = __float2bfloat16_rn(v.y);
    __nv_bfloat16 h2 = __float2bfloat16_rn(v.z);
    __nv_bfloat16 h3 = __float2bfloat16_rn(v.w);
    __nv_bfloat16 l0 = __float2bfloat16_rn(v.x - __bfloat162float(h0));
    __nv_bfloat16 l1 = __float2bfloat16_rn(v.y - __bfloat162float(h1));
    __nv_bfloat16 l2 = __float2bfloat16_rn(v.z - __bfloat162float(h2));
    __nv_bfloat16 l3 = __float2bfloat16_rn(v.w - __bfloat162float(h3));
    *(__nv_bfloat162*)&g_xhi[i]     = __halves2bfloat162(h0, h1);
    *(__nv_bfloat162*)&g_xhi[i + 2] = __halves2bfloat162(h2, h3);
    *(__nv_bfloat162*)&g_xlo[i]     = __halves2bfloat162(l0, l1);
    *(__nv_bfloat162*)&g_xlo[i + 2] = __halves2bfloat162(l2, l3);
}

// =====================================================================
// Kernel 3: reps -> bf16 hi/lo + transposed hi/lo
// =====================================================================
__global__ void trans_kernel() {
    __shared__ float tile[32][33];
    const int r0 = blockIdx.x * 32;     // NF dim
    const int c0 = blockIdx.y * 32;     // DIM dim
    const int tid = threadIdx.x;
    #pragma unroll
    for (int i = 0; i < 4; ++i) {
        const int idx = tid + i * 256;
        const int rr = idx >> 5, cc = idx & 31;
        const float v = g_reps[(r0 + rr) * DIM + c0 + cc];
        tile[rr][cc] = v;
        __nv_bfloat16 h = __float2bfloat16_rn(v);
        g_bhi[(r0 + rr) * DIM + c0 + cc] = h;
        g_blo[(r0 + rr) * DIM + c0 + cc] =
            __float2bfloat16_rn(v - __bfloat162float(h));
    }
    __syncthreads();
    #pragma unroll
    for (int i = 0; i < 4; ++i) {
        const int idx = tid + i * 256;
        const int rr = idx >> 5, cc = idx & 31;
        const float v = tile[cc][rr];
        __nv_bfloat16 h = __float2bfloat16_rn(v);
        g_bthi[(size_t)(c0 + rr) * NF + r0 + cc] = h;
        g_btlo[(size_t)(c0 + rr) * NF + r0 + cc] =
            __float2bfloat16_rn(v - __bfloat162float(h));
    }
}

// =====================================================================
// Tile copy: A/B each 128 rows x 32 bf16, hi+lo, swizzled. One commit group.
// =====================================================================
__device__ __forceinline__ void copy_tiles(
    uint32_t base, int tid,
    const __nv_bfloat16* Ah, const __nv_bfloat16* Al, size_t ap,
    const __nv_bfloat16* Bh, const __nv_bfloat16* Bl, size_t bp) {
    #pragma unroll
    for (int p = 0; p < 2; ++p) {
        const int idx = tid + p * 256;       // 512 chunks
        const int r = idx >> 2, c = idx & 3;
        const uint32_t off = tswz(r, c);
        const size_t g = (size_t)r;
        cp16(base + OFF_AH + off, Ah + g * ap + c * 8);
        cp16(base + OFF_AL + off, Al + g * ap + c * 8);
        cp16(base + OFF_BH + off, Bh + g * bp + c * 8);
        cp16(base + OFF_BL + off, Bl + g * bp + c * 8);
    }
    cp_commit();
}

// =====================================================================
// mainloop macro: BM=128 BN=128 BK=32, 8 warps (2Mx4N), warp tile 64x32,
// bf16 3-split (AhBh + AhBl + AlBh), fp32 acc[4][4][4].
// 3-stage cp.async pipeline, one __syncthreads per iteration.
// =====================================================================
#define GEMM_MAINLOOP(sb, tid, Ah, Al, AP, Bh, Bl, BP, NT, acc)                       \
{                                                                                     \
    const int lane = (tid) & 31, warp = (tid) >> 5;                                   \
    const int wm = warp & 1, wn = warp >> 1;                                          \
    const int rsub = lane & 15, csub = lane >> 4;                                     \
    int arow[4], brow[2];                                                             \
    _Pragma("unroll") for (int i = 0; i < 4; ++i) arow[i] = wm * 64 + i * 16 + rsub;  \
    _Pragma("unroll") for (int j = 0; j < 2; ++j) brow[j] = wn * 32 + j * 16 + rsub;  \
    copy_tiles((sb), (tid), (Ah), (Al), (AP), (Bh), (Bl), (BP));                      \
    copy_tiles((sb) + BUF_STRIDE, (tid),                                              \
               (Ah) + 32, (Al) + 32, (AP), (Bh) + 32, (Bl) + 32, (BP));               \
    int bufi = 0;                                                                     \
    for (int t = 0; t < (NT); ++t) {                                                  \
        const uint32_t cb_ = (sb) + (uint32_t)bufi * BUF_STRIDE;                      \
        if (t + 1 < (NT)) cp_wait1(); else cp_wait0();                                \
        __syncthreads();                                                              \
        if (t + 2 < (NT)) {                                                           \
            const int kc = (t + 2) * 32;                                              \
            int wbuf = bufi + 2; if (wbuf >= N_STAGES) wbuf -= N_STAGES;              \
            copy_tiles((sb) + (uint32_t)wbuf * BUF_STRIDE, (tid),                     \
                       (Ah) + kc, (Al) + kc, (AP), (Bh) + kc, (Bl) + kc, (BP));       \
        }                                                                             \
        _Pragma("unroll") for (int h = 0; h < 2; ++h) {                               \
            uint32_t ah[4][4], al[4][4], bh[2][4], bl[2][4];                          \
            _Pragma("unroll") for (int i = 0; i < 4; ++i) {                           \
                const uint32_t ao = tswz(arow[i], 2 * h + csub);                      \
                ldsm4(ah[i][0], ah[i][1], ah[i][2], ah[i][3], cb_ + OFF_AH + ao);     \
                ldsm4(al[i][0], al[i][1], al[i][2], al[i][3], cb_ + OFF_AL + ao);     \
            }                                                                         \
            _Pragma("unroll") for (int j = 0; j < 2; ++j) {                           \
                const uint32_t bo = tswz(brow[j], 2 * h + csub);                      \
                ldsm4(bh[j][0], bh[j][1], bh[j][2], bh[j][3], cb_ + OFF_BH + bo);     \
                ldsm4(bl[j][0], bl[j][1], bl[j][2], bl[j][3], cb_ + OFF_BL + bo);     \
            }                                                                         \
            _Pragma("unroll") for (int i = 0; i < 4; ++i)                             \
            _Pragma("unroll") for (int j2 = 0; j2 < 2; ++j2)                          \
            _Pragma("unroll") for (int s = 0; s < 2; ++s) {                           \
                float* d = acc[i][j2 * 2 + s];                                        \
                mma16816(d, ah[i], bh[j2][s], bh[j2][s + 2]);                         \
                mma16816(d, ah[i], bl[j2][s], bl[j2][s + 2]);                         \
                mma16816(d, al[i], bh[j2][s], bh[j2][s + 2]);                         \
            }                                                                         \
        }                                                                             \
        if (++bufi >= N_STAGES) bufi = 0;                                             \
    }                                                                                 \
}

// =====================================================================
// Kernel 4: gemm2: partial[bz] = X[:,kslice] @ reps[kslice,:]  (split-K=4)
// =====================================================================
__global__ void __launch_bounds__(256, 2) gemm2_mm(void) {
    extern __shared__ char smem[];
    const uint32_t sb = smem_u32(smem);
    const int tid = threadIdx.x;
    const int bm = blockIdx.x, bn = blockIdx.y, bz = blockIdx.z;
    const int k0 = bz * (NF / SK2);
    const int NT = (NF / SK2) / 32;         // 64

    float acc[4][4][4];
    #pragma unroll
    for (int i = 0; i < 4; ++i)
        #pragma unroll
        for (int j = 0; j < 4; ++j)
            #pragma unroll
            for (int s = 0; s < 4; ++s) acc[i][j][s] = 0.0f;

    const __nv_bfloat16* Ah = g_xhi + (size_t)(bm * 128) * NF + k0;
    const __nv_bfloat16* Al = g_xlo + (size_t)(bm * 128) * NF + k0;
    const __nv_bfloat16* Bh = g_bthi + (size_t)(bn * 128) * NF + k0;
    const __nv_bfloat16* Bl = g_btlo + (size_t)(bn * 128) * NF + k0;

    GEMM_MAINLOOP(sb, tid, Ah, Al, NF, Bh, Bl, NF, NT, acc);

    const int lane = tid & 31, warp = tid >> 5;
    const int wm = warp & 1, wn = warp >> 1;
    float* P = g_part[bz];
    const int l4 = lane >> 2, l2 = (lane & 3) * 2;
    #pragma unroll
    for (int i = 0; i < 4; ++i) {
        const int r0 = bm * 128 + wm * 64 + i * 16 + l4;
        #pragma unroll
        for (int j = 0; j < 4; ++j) {
            const int n = bn * 128 + wn * 32 + j * 8 + l2;
            *(float2*)&P[(size_t)r0 * DIM + n]       = make_float2(acc[i][j][0], acc[i][j][1]);
            *(float2*)&P[(size_t)(r0 + 8) * DIM + n] = make_float2(acc[i][j][2], acc[i][j][3]);
        }
    }
}

// =====================================================================
// Kernel 5: sum split-K partials -> hidden bf16 hi/lo
// =====================================================================
__global__ void hconv_kernel() {
    const size_t i = ((size_t)blockIdx.x * 256 + threadIdx.x) * 4;
    float4 s = *(const float4*)&g_part[0][i];
    #pragma unroll
    for (int z = 1; z < SK2; ++z) {
        float4 p = *(const float4*)&g_part[z][i];
        s.x += p.x; s.y += p.y; s.z += p.z; s.w += p.w;
    }
    __nv_bfloat16 h0 = __float2bfloat16_rn(s.x);
    __nv_bfloat16 h1 = __float2bfloat16_rn(s.y);
    __nv_bfloat16 h2 = __float2bfloat16_rn(s.z);
    __nv_bfloat16 h3 = __float2bfloat16_rn(s.w);
    __nv_bfloat16 l0 = __float2bfloat16_rn(s.x - __bfloat162float(h0));
    __nv_bfloat16 l1 = __float2bfloat16_rn(s.y - __bfloat162float(h1));
    __nv_bfloat16 l2 = __float2bfloat16_rn(s.z - __bfloat162float(h2));
    __nv_bfloat16 l3 = __float2bfloat16_rn(s.w - __bfloat162float(h3));
    *(__nv_bfloat162*)&g_ahi[i]     = __halves2bfloat162(h0, h1);
    *(__nv_bfloat162*)&g_ahi[i + 2] = __halves2bfloat162(h2, h3);
    *(__nv_bfloat162*)&g_alo[i]     = __halves2bfloat162(l0, l1);
    *(__nv_bfloat162*)&g_alo[i + 2] = __halves2bfloat162(l2, l3);
}

// =====================================================================
// Kernel 6: gemm3: out = relu(hidden @ reps^T + bias)
// =====================================================================
__global__ void __launch_bounds__(256, 2) gemm3_mm(const float* __restrict__ bias,
                                                   float* __restrict__ out) {
    extern __shared__ char smem[];
    const uint32_t sb = smem_u32(smem);
    const int tid = threadIdx.x;
    const int bm = blockIdx.x, bn = blockIdx.y;
    const int NT = DIM / 32;                // 8

    float acc[4][4][4];
    #pragma unroll
    for (int i = 0; i < 4; ++i)
        #pragma unroll
        for (int j = 0; j < 4; ++j)
            #pragma unroll
            for (int s = 0; s < 4; ++s) acc[i][j][s] = 0.0f;

    const __nv_bfloat16* Ah = g_ahi + (size_t)(bm * 128) * DIM;
    const __nv_bfloat16* Al = g_alo + (size_t)(bm * 128) * DIM;
    const __nv_bfloat16* Bh = g_bhi + (size_t)(bn * 128) * DIM;
    const __nv_bfloat16* Bl = g_blo + (size_t)(bn * 128) * DIM;

    GEMM_MAINLOOP(sb, tid, Ah, Al, DIM, Bh, Bl, DIM, NT, acc);

    const int lane = tid & 31, warp = tid >> 5;
    const int wm = warp & 1, wn = warp >> 1;
    const int l4 = lane >> 2, l2 = (lane & 3) * 2;
    #pragma unroll
    for (int i = 0; i < 4; ++i) {
        const int r0 = bm * 128 + wm * 64 + i * 16 + l4;
        #pragma unroll
        for (int j = 0; j < 4; ++j) {
            const int n = bn * 128 + wn * 32 + j * 8 + l2;
            const float b0 = bias[n], b1 = bias[n + 1];
            float2 v0 = make_float2(fmaxf(acc[i][j][0] + b0, 0.0f),
                                    fmaxf(acc[i][j][1] + b1, 0.0f));
            float2 v1 = make_float2(fmaxf(acc[i][j][2] + b0, 0.0f),
                                    fmaxf(acc[i][j][3] + b1, 0.0f));
            *(float2*)&out[(size_t)r0 * NF + n]       = v0;
            *(float2*)&out[(size_t)(r0 + 8) * NF + n] = v1;
        }
    }
}

// =====================================================================
extern "C" void kernel_launch(void* const* d_in, const int* in_sizes, int n_in,
                              void* d_out, int out_size) {
    const float* x    = (const float*)d_in[0];
    const float* proj = (const float*)d_in[1];
    const float* rw   = (const float*)d_in[2];
    const float* rb   = (const float*)d_in[3];
    const float* cb   = (const float*)d_in[4];
    const float* bias = (const float*)d_in[5];
    float* out = (float*)d_out;

    const int wbytes = HEADS * CELLS * DIM * (int)sizeof(float);   // 128 KB
    cudaFuncSetAttribute((const void*)reps_kernel,
                         cudaFuncAttributeMaxDynamicSharedMemorySize, wbytes);
    cudaFuncSetAttribute((const void*)gemm2_mm,
                         cudaFuncAttributeMaxDynamicSharedMemorySize, GEMM_SMEM);
    cudaFuncSetAttribute((const void*)gemm3_mm,
                         cudaFuncAttributeMaxDynamicSharedMemorySize, GEMM_SMEM);

    cvtx_kernel<<<(int)(((size_t)BATCH * NF / 4) / 256), 256>>>(x);
    reps_kernel<<<148, 256, wbytes>>>(proj, rw, rb, cb);
    trans_kernel<<<dim3(NF / 32, DIM / 32), 256>>>();

    gemm2_mm<<<dim3(BATCH / 128, DIM / 128, SK2), 256, GEMM_SMEM>>>();
    hconv_kernel<<<(BATCH * DIM / 4) / 256, 256>>>();
    gemm3_mm<<<dim3(BATCH / 128, NF / 128), 256, GEMM_SMEM>>>(bias, out);
}

// round 9
// speedup vs baseline: 3.6946x; 1.0051x over previous
#include <cuda_runtime.h>
#include <cuda_bf16.h>
#include <cstdint>

#define BATCH 4096
#define NF    8192
#define DIM   256
#define HEADS 4
#define CELLS 32
#define SK2   8            // gemm2 split-K

// ---------------- scratch (device globals; no allocs allowed) ----------------
__device__ __align__(16) __nv_bfloat16 g_xhi[(size_t)BATCH * NF];
__device__ __align__(16) __nv_bfloat16 g_xlo[(size_t)BATCH * NF];
__device__ float g_reps[NF * DIM];
__device__ __align__(16) __nv_bfloat16 g_bhi[NF * DIM];    // reps   [NF][DIM]
__device__ __align__(16) __nv_bfloat16 g_blo[NF * DIM];
__device__ __align__(16) __nv_bfloat16 g_bthi[DIM * NF];   // reps^T [DIM][NF]
__device__ __align__(16) __nv_bfloat16 g_btlo[DIM * NF];
__device__ float g_part[SK2][(size_t)BATCH * DIM];
__device__ __align__(16) __nv_bfloat16 g_ahi[BATCH * DIM];
__device__ __align__(16) __nv_bfloat16 g_alo[BATCH * DIM];

// ---------------- PTX helpers (base ISA only) ----------------
__device__ __forceinline__ uint32_t smem_u32(const void* p) {
    uint32_t a;
    asm("{ .reg .u64 t; cvta.to.shared.u64 t, %1; cvt.u32.u64 %0, t; }" : "=r"(a) : "l"(p));
    return a;
}
__device__ __forceinline__ void cp16(uint32_t d, const void* s) {
    asm volatile("cp.async.cg.shared.global [%0], [%1], 16;" :: "r"(d), "l"(s));
}
__device__ __forceinline__ void cp_commit() {
    asm volatile("cp.async.commit_group;" ::: "memory");
}
__device__ __forceinline__ void cp_wait0() {
    asm volatile("cp.async.wait_group 0;" ::: "memory");
}
__device__ __forceinline__ void cp_wait1() {
    asm volatile("cp.async.wait_group 1;" ::: "memory");
}
// NOTE: no volatile — outputs make these live; lets ptxas schedule freely.
__device__ __forceinline__ void ldsm4(uint32_t& r0, uint32_t& r1, uint32_t& r2,
                                      uint32_t& r3, uint32_t a) {
    asm("ldmatrix.sync.aligned.m8n8.x4.shared.b16 {%0,%1,%2,%3}, [%4];"
        : "=r"(r0), "=r"(r1), "=r"(r2), "=r"(r3) : "r"(a));
}
__device__ __forceinline__ void mma16816(float* d, const uint32_t* a,
                                         uint32_t b0, uint32_t b1) {
    asm("mma.sync.aligned.m16n8k16.row.col.f32.bf16.bf16.f32 "
        "{%0,%1,%2,%3}, {%4,%5,%6,%7}, {%8,%9}, {%0,%1,%2,%3};"
        : "+f"(d[0]), "+f"(d[1]), "+f"(d[2]), "+f"(d[3])
        : "r"(a[0]), "r"(a[1]), "r"(a[2]), "r"(a[3]), "r"(b0), "r"(b1));
}

// smem tile: 128 rows x 32 bf16 (4 16B chunks/row), chunk swizzle
#define OFF_AH 0
#define OFF_AL 8192
#define OFF_BH 16384
#define OFF_BL 24576
#define BUF_STRIDE 32768
#define N_STAGES 3
#define GEMM_SMEM (N_STAGES * BUF_STRIDE)    // 96 KB

__device__ __forceinline__ uint32_t tswz(int r, int c) {
    return (uint32_t)(r * 64 + ((c ^ ((r >> 1) & 3)) << 4));
}

// =====================================================================
// Kernel 1: reps (proven)
// =====================================================================
__global__ void reps_kernel(const float* __restrict__ proj,
                            const float* __restrict__ rw,
                            const float* __restrict__ rb,
                            const float* __restrict__ cb) {
    extern __shared__ float Wsh[];
    __shared__ float lat[DIM];
    __shared__ float sc[HEADS * CELLS];
    __shared__ float g_sh[HEADS];
    __shared__ int   w_sh[HEADS];
    __shared__ int   r_sh[HEADS];

    const int tid  = threadIdx.x;
    const int lane = tid & 31;
    const int warp = tid >> 5;

    for (int i = tid; i < HEADS * CELLS * DIM; i += 256)
        Wsh[i] = rw[i];
    __syncthreads();

    for (int row = blockIdx.x; row < NF; row += gridDim.x) {
        lat[tid] = proj[row * DIM + tid];
        __syncthreads();

        float la[8];
        #pragma unroll
        for (int i = 0; i < 8; ++i) la[i] = lat[lane + 32 * i];

        #pragma unroll 1
        for (int pi = 0; pi < 16; ++pi) {
            const int p = warp * 16 + pi;
            const float* wrow = &Wsh[p * DIM];
            float m = -3.4e38f;
            #pragma unroll
            for (int i = 0; i < 8; ++i)
                m = fmaxf(m, la[i] + wrow[lane + 32 * i]);
            #pragma unroll
            for (int off = 16; off >= 1; off >>= 1)
                m = fmaxf(m, __shfl_xor_sync(0xffffffffu, m, off));
            if (lane == 0) sc[p] = m + rb[p];
        }
        __syncthreads();

        if (warp < HEADS) {
            const float s = sc[warp * CELLS + lane];
            float v = s; int idx = lane;
            #pragma unroll
            for (int off = 16; off >= 1; off >>= 1) {
                float ov = __shfl_xor_sync(0xffffffffu, v, off);
                int   oi = __shfl_xor_sync(0xffffffffu, idx, off);
                if (ov > v || (ov == v && oi < idx)) { v = ov; idx = oi; }
            }
            const float v1 = v; const int i1 = idx;
            v = (lane == i1) ? -3.4e38f : s; idx = lane;
            #pragma unroll
            for (int off = 16; off >= 1; off >>= 1) {
                float ov = __shfl_xor_sync(0xffffffffu, v, off);
                int   oi = __shfl_xor_sync(0xffffffffu, idx, off);
                if (ov > v || (ov == v && oi < idx)) { v = ov; idx = oi; }
            }
            if (lane == 0) {
                g_sh[warp] = 1.0f / (1.0f + expf(-(v1 - v)));
                w_sh[warp] = i1;
                r_sh[warp] = idx;
            }
        }
        __syncthreads();

        float acc = lat[tid];
        #pragma unroll
        for (int h = 0; h < HEADS; ++h) {
            const float g = g_sh[h];
            acc += g          * cb[(h * CELLS + w_sh[h]) * DIM + tid]
                 + (1.0f - g) * cb[(h * CELLS + r_sh[h]) * DIM + tid];
        }
        g_reps[row * DIM + tid] = acc;
        __syncthreads();
    }
}

// =====================================================================
// Kernel 2: x -> bf16 hi/lo
// =====================================================================
__global__ void cvtx_kernel(const float* __restrict__ x) {
    const size_t i = ((size_t)blockIdx.x * 256 + threadIdx.x) * 4;
    float4 v = *(const float4*)(x + i);
    __nv_bfloat16 h0 = __float2bfloat16_rn(v.x);
    __nv_bfloat16 h1 = __float2bfloat16_rn(v.y);
    __nv_bfloat16 h2 = __float2bfloat16_rn(v.z);
    __nv_bfloat16 h3 = __float2bfloat16_rn(v.w);
    __nv_bfloat16 l0 = __float2bfloat16_rn(v.x - __bfloat162float(h0));
    __nv_bfloat16 l1 = __float2bfloat16_rn(v.y - __bfloat162float(h1));
    __nv_bfloat16 l2 = __float2bfloat16_rn(v.z - __bfloat162float(h2));
    __nv_bfloat16 l3 = __float2bfloat16_rn(v.w - __bfloat162float(h3));
    *(__nv_bfloat162*)&g_xhi[i]     = __halves2bfloat162(h0, h1);
    *(__nv_bfloat162*)&g_xhi[i + 2] = __halves2bfloat162(h2, h3);
    *(__nv_bfloat162*)&g_xlo[i]     = __halves2bfloat162(l0, l1);
    *(__nv_bfloat162*)&g_xlo[i + 2] = __halves2bfloat162(l2, l3);
}

// =====================================================================
// Kernel 3: reps -> bf16 hi/lo + transposed hi/lo
// =====================================================================
__global__ void trans_kernel() {
    __shared__ float tile[32][33];
    const int r0 = blockIdx.x * 32;     // NF dim
    const int c0 = blockIdx.y * 32;     // DIM dim
    const int tid = threadIdx.x;
    #pragma unroll
    for (int i = 0; i < 4; ++i) {
        const int idx = tid + i * 256;
        const int rr = idx >> 5, cc = idx & 31;
        const float v = g_reps[(r0 + rr) * DIM + c0 + cc];
        tile[rr][cc] = v;
        __nv_bfloat16 h = __float2bfloat16_rn(v);
        g_bhi[(r0 + rr) * DIM + c0 + cc] = h;
        g_blo[(r0 + rr) * DIM + c0 + cc] =
            __float2bfloat16_rn(v - __bfloat162float(h));
    }
    __syncthreads();
    #pragma unroll
    for (int i = 0; i < 4; ++i) {
        const int idx = tid + i * 256;
        const int rr = idx >> 5, cc = idx & 31;
        const float v = tile[cc][rr];
        __nv_bfloat16 h = __float2bfloat16_rn(v);
        g_bthi[(size_t)(c0 + rr) * NF + r0 + cc] = h;
        g_btlo[(size_t)(c0 + rr) * NF + r0 + cc] =
            __float2bfloat16_rn(v - __bfloat162float(h));
    }
}

// =====================================================================
// Tile copy: A/B each 128 rows x 32 bf16, hi+lo, swizzled. One commit group.
// =====================================================================
__device__ __forceinline__ void copy_tiles(
    uint32_t base, int tid,
    const __nv_bfloat16* Ah, const __nv_bfloat16* Al, size_t ap,
    const __nv_bfloat16* Bh, const __nv_bfloat16* Bl, size_t bp) {
    #pragma unroll
    for (int p = 0; p < 2; ++p) {
        const int idx = tid + p * 256;       // 512 chunks
        const int r = idx >> 2, c = idx & 3;
        const uint32_t off = tswz(r, c);
        const size_t g = (size_t)r;
        cp16(base + OFF_AH + off, Ah + g * ap + c * 8);
        cp16(base + OFF_AL + off, Al + g * ap + c * 8);
        cp16(base + OFF_BH + off, Bh + g * bp + c * 8);
        cp16(base + OFF_BL + off, Bl + g * bp + c * 8);
    }
    cp_commit();
}

// =====================================================================
// mainloop macro: BM=128 BN=128 BK=32, 8 warps (2Mx4N), warp tile 64x32,
// bf16 3-split. MMAs issued in 3 passes of 16 INDEPENDENT ops each so no
// back-to-back RAW chains (was the R8 issue-limiter).
// 3-stage cp.async pipeline, one __syncthreads per iteration.
// =====================================================================
#define GEMM_MAINLOOP(sb, tid, Ah, Al, AP, Bh, Bl, BP, NT, acc)                       \
{                                                                                     \
    const int lane = (tid) & 31, warp = (tid) >> 5;                                   \
    const int wm = warp & 1, wn = warp >> 1;                                          \
    const int rsub = lane & 15, csub = lane >> 4;                                     \
    int arow[4], brow[2];                                                             \
    _Pragma("unroll") for (int i = 0; i < 4; ++i) arow[i] = wm * 64 + i * 16 + rsub;  \
    _Pragma("unroll") for (int j = 0; j < 2; ++j) brow[j] = wn * 32 + j * 16 + rsub;  \
    copy_tiles((sb), (tid), (Ah), (Al), (AP), (Bh), (Bl), (BP));                      \
    copy_tiles((sb) + BUF_STRIDE, (tid),                                              \
               (Ah) + 32, (Al) + 32, (AP), (Bh) + 32, (Bl) + 32, (BP));               \
    int bufi = 0;                                                                     \
    for (int t = 0; t < (NT); ++t) {                                                  \
        const uint32_t cb_ = (sb) + (uint32_t)bufi * BUF_STRIDE;                      \
        if (t + 1 < (NT)) cp_wait1(); else cp_wait0();                                \
        __syncthreads();                                                              \
        if (t + 2 < (NT)) {                                                           \
            const int kc = (t + 2) * 32;                                              \
            int wbuf = bufi + 2; if (wbuf >= N_STAGES) wbuf -= N_STAGES;              \
            copy_tiles((sb) + (uint32_t)wbuf * BUF_STRIDE, (tid),                     \
                       (Ah) + kc, (Al) + kc, (AP), (Bh) + kc, (Bl) + kc, (BP));       \
        }                                                                             \
        _Pragma("unroll") for (int h = 0; h < 2; ++h) {                               \
            uint32_t ah[4][4], al[4][4], bh[2][4], bl[2][4];                          \
            _Pragma("unroll") for (int i = 0; i < 4; ++i) {                           \
                const uint32_t ao = tswz(arow[i], 2 * h + csub);                      \
                ldsm4(ah[i][0], ah[i][1], ah[i][2], ah[i][3], cb_ + OFF_AH + ao);     \
                ldsm4(al[i][0], al[i][1], al[i][2], al[i][3], cb_ + OFF_AL + ao);     \
            }                                                                         \
            _Pragma("unroll") for (int j = 0; j < 2; ++j) {                           \
                const uint32_t bo = tswz(brow[j], 2 * h + csub);                      \
                ldsm4(bh[j][0], bh[j][1], bh[j][2], bh[j][3], cb_ + OFF_BH + bo);     \
                ldsm4(bl[j][0], bl[j][1], bl[j][2], bl[j][3], cb_ + OFF_BL + bo);     \
            }                                                                         \
            /* pass 1: Ah*Bh — 16 independent MMAs */                                 \
            _Pragma("unroll") for (int i = 0; i < 4; ++i)                             \
            _Pragma("unroll") for (int j2 = 0; j2 < 2; ++j2)                          \
            _Pragma("unroll") for (int s = 0; s < 2; ++s)                             \
                mma16816(acc[i][j2 * 2 + s], ah[i], bh[j2][s], bh[j2][s + 2]);        \
            /* pass 2: Ah*Bl — 16 independent MMAs */                                 \
            _Pragma("unroll") for (int i = 0; i < 4; ++i)                             \
            _Pragma("unroll") for (int j2 = 0; j2 < 2; ++j2)                          \
            _Pragma("unroll") for (int s = 0; s < 2; ++s)                             \
                mma16816(acc[i][j2 * 2 + s], ah[i], bl[j2][s], bl[j2][s + 2]);        \
            /* pass 3: Al*Bh — 16 independent MMAs */                                 \
            _Pragma("unroll") for (int i = 0; i < 4; ++i)                             \
            _Pragma("unroll") for (int j2 = 0; j2 < 2; ++j2)                          \
            _Pragma("unroll") for (int s = 0; s < 2; ++s)                             \
                mma16816(acc[i][j2 * 2 + s], al[i], bh[j2][s], bh[j2][s + 2]);        \
        }                                                                             \
        if (++bufi >= N_STAGES) bufi = 0;                                             \
    }                                                                                 \
}

// =====================================================================
// Kernel 4: gemm2: partial[bz] = X[:,kslice] @ reps[kslice,:]  (split-K=8)
// =====================================================================
__global__ void __launch_bounds__(256, 2) gemm2_mm(void) {
    extern __shared__ char smem[];
    const uint32_t sb = smem_u32(smem);
    const int tid = threadIdx.x;
    const int bm = blockIdx.x, bn = blockIdx.y, bz = blockIdx.z;
    const int k0 = bz * (NF / SK2);
    const int NT = (NF / SK2) / 32;         // 32

    float acc[4][4][4];
    #pragma unroll
    for (int i = 0; i < 4; ++i)
        #pragma unroll
        for (int j = 0; j < 4; ++j)
            #pragma unroll
            for (int s = 0; s < 4; ++s) acc[i][j][s] = 0.0f;

    const __nv_bfloat16* Ah = g_xhi + (size_t)(bm * 128) * NF + k0;
    const __nv_bfloat16* Al = g_xlo + (size_t)(bm * 128) * NF + k0;
    const __nv_bfloat16* Bh = g_bthi + (size_t)(bn * 128) * NF + k0;
    const __nv_bfloat16* Bl = g_btlo + (size_t)(bn * 128) * NF + k0;

    GEMM_MAINLOOP(sb, tid, Ah, Al, NF, Bh, Bl, NF, NT, acc);

    const int lane = tid & 31, warp = tid >> 5;
    const int wm = warp & 1, wn = warp >> 1;
    float* P = g_part[bz];
    const int l4 = lane >> 2, l2 = (lane & 3) * 2;
    #pragma unroll
    for (int i = 0; i < 4; ++i) {
        const int r0 = bm * 128 + wm * 64 + i * 16 + l4;
        #pragma unroll
        for (int j = 0; j < 4; ++j) {
            const int n = bn * 128 + wn * 32 + j * 8 + l2;
            *(float2*)&P[(size_t)r0 * DIM + n]       = make_float2(acc[i][j][0], acc[i][j][1]);
            *(float2*)&P[(size_t)(r0 + 8) * DIM + n] = make_float2(acc[i][j][2], acc[i][j][3]);
        }
    }
}

// =====================================================================
// Kernel 5: sum split-K partials -> hidden bf16 hi/lo
// =====================================================================
__global__ void hconv_kernel() {
    const size_t i = ((size_t)blockIdx.x * 256 + threadIdx.x) * 4;
    float4 s = *(const float4*)&g_part[0][i];
    #pragma unroll
    for (int z = 1; z < SK2; ++z) {
        float4 p = *(const float4*)&g_part[z][i];
        s.x += p.x; s.y += p.y; s.z += p.z; s.w += p.w;
    }
    __nv_bfloat16 h0 = __float2bfloat16_rn(s.x);
    __nv_bfloat16 h1 = __float2bfloat16_rn(s.y);
    __nv_bfloat16 h2 = __float2bfloat16_rn(s.z);
    __nv_bfloat16 h3 = __float2bfloat16_rn(s.w);
    __nv_bfloat16 l0 = __float2bfloat16_rn(s.x - __bfloat162float(h0));
    __nv_bfloat16 l1 = __float2bfloat16_rn(s.y - __bfloat162float(h1));
    __nv_bfloat16 l2 = __float2bfloat16_rn(s.z - __bfloat162float(h2));
    __nv_bfloat16 l3 = __float2bfloat16_rn(s.w - __bfloat162float(h3));
    *(__nv_bfloat162*)&g_ahi[i]     = __halves2bfloat162(h0, h1);
    *(__nv_bfloat162*)&g_ahi[i + 2] = __halves2bfloat162(h2, h3);
    *(__nv_bfloat162*)&g_alo[i]     = __halves2bfloat162(l0, l1);
    *(__nv_bfloat162*)&g_alo[i + 2] = __halves2bfloat162(l2, l3);
}

// =====================================================================
// Kernel 6: gemm3: out = relu(hidden @ reps^T + bias)
// =====================================================================
__global__ void __launch_bounds__(256, 2) gemm3_mm(const float* __restrict__ bias,
                                                   float* __restrict__ out) {
    extern __shared__ char smem[];
    const uint32_t sb = smem_u32(smem);
    const int tid = threadIdx.x;
    const int bm = blockIdx.x, bn = blockIdx.y;
    const int NT = DIM / 32;                // 8

    float acc[4][4][4];
    #pragma unroll
    for (int i = 0; i < 4; ++i)
        #pragma unroll
        for (int j = 0; j < 4; ++j)
            #pragma unroll
            for (int s = 0; s < 4; ++s) acc[i][j][s] = 0.0f;

    const __nv_bfloat16* Ah = g_ahi + (size_t)(bm * 128) * DIM;
    const __nv_bfloat16* Al = g_alo + (size_t)(bm * 128) * DIM;
    const __nv_bfloat16* Bh = g_bhi + (size_t)(bn * 128) * DIM;
    const __nv_bfloat16* Bl = g_blo + (size_t)(bn * 128) * DIM;

    GEMM_MAINLOOP(sb, tid, Ah, Al, DIM, Bh, Bl, DIM, NT, acc);

    const int lane = tid & 31, warp = tid >> 5;
    const int wm = warp & 1, wn = warp >> 1;
    const int l4 = lane >> 2, l2 = (lane & 3) * 2;
    #pragma unroll
    for (int i = 0; i < 4; ++i) {
        const int r0 = bm * 128 + wm * 64 + i * 16 + l4;
        #pragma unroll
        for (int j = 0; j < 4; ++j) {
            const int n = bn * 128 + wn * 32 + j * 8 + l2;
            const float b0 = bias[n], b1 = bias[n + 1];
            float2 v0 = make_float2(fmaxf(acc[i][j][0] + b0, 0.0f),
                                    fmaxf(acc[i][j][1] + b1, 0.0f));
            float2 v1 = make_float2(fmaxf(acc[i][j][2] + b0, 0.0f),
                                    fmaxf(acc[i][j][3] + b1, 0.0f));
            *(float2*)&out[(size_t)r0 * NF + n]       = v0;
            *(float2*)&out[(size_t)(r0 + 8) * NF + n] = v1;
        }
    }
}

// =====================================================================
extern "C" void kernel_launch(void* const* d_in, const int* in_sizes, int n_in,
                              void* d_out, int out_size) {
    const float* x    = (const float*)d_in[0];
    const float* proj = (const float*)d_in[1];
    const float* rw   = (const float*)d_in[2];
    const float* rb   = (const float*)d_in[3];
    const float* cb   = (const float*)d_in[4];
    const float* bias = (const float*)d_in[5];
    float* out = (float*)d_out;

    const int wbytes = HEADS * CELLS * DIM * (int)sizeof(float);   // 128 KB
    cudaFuncSetAttribute((const void*)reps_kernel,
                         cudaFuncAttributeMaxDynamicSharedMemorySize, wbytes);
    cudaFuncSetAttribute((const void*)gemm2_mm,
                         cudaFuncAttributeMaxDynamicSharedMemorySize, GEMM_SMEM);
    cudaFuncSetAttribute((const void*)gemm3_mm,
                         cudaFuncAttributeMaxDynamicSharedMemorySize, GEMM_SMEM);

    cvtx_kernel<<<(int)(((size_t)BATCH * NF / 4) / 256), 256>>>(x);
    reps_kernel<<<148, 256, wbytes>>>(proj, rw, rb, cb);
    trans_kernel<<<dim3(NF / 32, DIM / 32), 256>>>();

    gemm2_mm<<<dim3(BATCH / 128, DIM / 128, SK2), 256, GEMM_SMEM>>>();
    hconv_kernel<<<(BATCH * DIM / 4) / 256, 256>>>();
    gemm3_mm<<<dim3(BATCH / 128, NF / 128), 256, GEMM_SMEM>>>(bias, out);
}

// round 10
// speedup vs baseline: 4.6102x; 1.2478x over previous
#include <cuda_runtime.h>
#include <cuda_bf16.h>
#include <cuda_fp16.h>
#include <cstdint>

#define BATCH 4096
#define NF    8192
#define DIM   256
#define HEADS 4
#define CELLS 32
#define SK2   8            // gemm2 split-K

// ---------------- scratch (device globals; no allocs allowed) ----------------
__device__ __align__(16) __half g_xh[(size_t)BATCH * NF];   // x fp16 (67 MB)
__device__ float g_reps[NF * DIM];
__device__ __align__(16) __half g_bh16[NF * DIM];           // reps   [NF][DIM] hi
__device__ __align__(16) __half g_bl16[NF * DIM];           // reps   [NF][DIM] lo
__device__ __align__(16) __half g_bth[DIM * NF];            // reps^T [DIM][NF] hi
__device__ __align__(16) __half g_btl[DIM * NF];            // reps^T [DIM][NF] lo
__device__ float g_part[SK2][(size_t)BATCH * DIM];
__device__ __align__(16) __half g_ah[BATCH * DIM];          // hidden fp16

// ---------------- PTX helpers (base ISA only) ----------------
__device__ __forceinline__ uint32_t smem_u32(const void* p) {
    uint32_t a;
    asm("{ .reg .u64 t; cvta.to.shared.u64 t, %1; cvt.u32.u64 %0, t; }" : "=r"(a) : "l"(p));
    return a;
}
__device__ __forceinline__ void cp16(uint32_t d, const void* s) {
    asm volatile("cp.async.cg.shared.global [%0], [%1], 16;" :: "r"(d), "l"(s));
}
__device__ __forceinline__ void cp_commit() {
    asm volatile("cp.async.commit_group;" ::: "memory");
}
__device__ __forceinline__ void cp_wait0() {
    asm volatile("cp.async.wait_group 0;" ::: "memory");
}
__device__ __forceinline__ void cp_wait1() {
    asm volatile("cp.async.wait_group 1;" ::: "memory");
}
__device__ __forceinline__ void ldsm4(uint32_t& r0, uint32_t& r1, uint32_t& r2,
                                      uint32_t& r3, uint32_t a) {
    asm("ldmatrix.sync.aligned.m8n8.x4.shared.b16 {%0,%1,%2,%3}, [%4];"
        : "=r"(r0), "=r"(r1), "=r"(r2), "=r"(r3) : "r"(a));
}
__device__ __forceinline__ void mma16816(float* d, const uint32_t* a,
                                         uint32_t b0, uint32_t b1) {
    asm("mma.sync.aligned.m16n8k16.row.col.f32.f16.f16.f32 "
        "{%0,%1,%2,%3}, {%4,%5,%6,%7}, {%8,%9}, {%0,%1,%2,%3};"
        : "+f"(d[0]), "+f"(d[1]), "+f"(d[2]), "+f"(d[3])
        : "r"(a[0]), "r"(a[1]), "r"(a[2]), "r"(a[3]), "r"(b0), "r"(b1));
}

// smem tile: 128 rows x 32 fp16 (4 16B chunks/row), chunk swizzle
#define OFF_A  0
#define OFF_BH 8192
#define OFF_BL 16384
#define BUF_STRIDE 24576
#define N_STAGES 3
#define GEMM_SMEM (N_STAGES * BUF_STRIDE)    // 72 KB

__device__ __forceinline__ uint32_t tswz(int r, int c) {
    return (uint32_t)(r * 64 + ((c ^ ((r >> 1) & 3)) << 4));
}

// =====================================================================
// Kernel 1: reps (proven)
// =====================================================================
__global__ void reps_kernel(const float* __restrict__ proj,
                            const float* __restrict__ rw,
                            const float* __restrict__ rb,
                            const float* __restrict__ cb) {
    extern __shared__ float Wsh[];
    __shared__ float lat[DIM];
    __shared__ float sc[HEADS * CELLS];
    __shared__ float g_sh[HEADS];
    __shared__ int   w_sh[HEADS];
    __shared__ int   r_sh[HEADS];

    const int tid  = threadIdx.x;
    const int lane = tid & 31;
    const int warp = tid >> 5;

    for (int i = tid; i < HEADS * CELLS * DIM; i += 256)
        Wsh[i] = rw[i];
    __syncthreads();

    for (int row = blockIdx.x; row < NF; row += gridDim.x) {
        lat[tid] = proj[row * DIM + tid];
        __syncthreads();

        float la[8];
        #pragma unroll
        for (int i = 0; i < 8; ++i) la[i] = lat[lane + 32 * i];

        #pragma unroll 1
        for (int pi = 0; pi < 16; ++pi) {
            const int p = warp * 16 + pi;
            const float* wrow = &Wsh[p * DIM];
            float m = -3.4e38f;
            #pragma unroll
            for (int i = 0; i < 8; ++i)
                m = fmaxf(m, la[i] + wrow[lane + 32 * i]);
            #pragma unroll
            for (int off = 16; off >= 1; off >>= 1)
                m = fmaxf(m, __shfl_xor_sync(0xffffffffu, m, off));
            if (lane == 0) sc[p] = m + rb[p];
        }
        __syncthreads();

        if (warp < HEADS) {
            const float s = sc[warp * CELLS + lane];
            float v = s; int idx = lane;
            #pragma unroll
            for (int off = 16; off >= 1; off >>= 1) {
                float ov = __shfl_xor_sync(0xffffffffu, v, off);
                int   oi = __shfl_xor_sync(0xffffffffu, idx, off);
                if (ov > v || (ov == v && oi < idx)) { v = ov; idx = oi; }
            }
            const float v1 = v; const int i1 = idx;
            v = (lane == i1) ? -3.4e38f : s; idx = lane;
            #pragma unroll
            for (int off = 16; off >= 1; off >>= 1) {
                float ov = __shfl_xor_sync(0xffffffffu, v, off);
                int   oi = __shfl_xor_sync(0xffffffffu, idx, off);
                if (ov > v || (ov == v && oi < idx)) { v = ov; idx = oi; }
            }
            if (lane == 0) {
                g_sh[warp] = 1.0f / (1.0f + expf(-(v1 - v)));
                w_sh[warp] = i1;
                r_sh[warp] = idx;
            }
        }
        __syncthreads();

        float acc = lat[tid];
        #pragma unroll
        for (int h = 0; h < HEADS; ++h) {
            const float g = g_sh[h];
            acc += g          * cb[(h * CELLS + w_sh[h]) * DIM + tid]
                 + (1.0f - g) * cb[(h * CELLS + r_sh[h]) * DIM + tid];
        }
        g_reps[row * DIM + tid] = acc;
        __syncthreads();
    }
}

// =====================================================================
// Kernel 2: x -> fp16 (single rounding)
// =====================================================================
__global__ void cvtx_kernel(const float* __restrict__ x) {
    const size_t i = ((size_t)blockIdx.x * 256 + threadIdx.x) * 8;
    float4 v0 = *(const float4*)(x + i);
    float4 v1 = *(const float4*)(x + i + 4);
    __half2 h01 = __floats2half2_rn(v0.x, v0.y);
    __half2 h23 = __floats2half2_rn(v0.z, v0.w);
    __half2 h45 = __floats2half2_rn(v1.x, v1.y);
    __half2 h67 = __floats2half2_rn(v1.z, v1.w);
    uint4 o;
    o.x = *(uint32_t*)&h01; o.y = *(uint32_t*)&h23;
    o.z = *(uint32_t*)&h45; o.w = *(uint32_t*)&h67;
    *(uint4*)&g_xh[i] = o;
}

// =====================================================================
// Kernel 3: reps -> fp16 hi/lo (straight + transposed)
// =====================================================================
__global__ void trans_kernel() {
    __shared__ float tile[32][33];
    const int r0 = blockIdx.x * 32;     // NF dim
    const int c0 = blockIdx.y * 32;     // DIM dim
    const int tid = threadIdx.x;
    #pragma unroll
    for (int i = 0; i < 4; ++i) {
        const int idx = tid + i * 256;
        const int rr = idx >> 5, cc = idx & 31;
        const float v = g_reps[(r0 + rr) * DIM + c0 + cc];
        tile[rr][cc] = v;
        __half h = __float2half_rn(v);
        g_bh16[(r0 + rr) * DIM + c0 + cc] = h;
        g_bl16[(r0 + rr) * DIM + c0 + cc] =
            __float2half_rn(v - __half2float(h));
    }
    __syncthreads();
    #pragma unroll
    for (int i = 0; i < 4; ++i) {
        const int idx = tid + i * 256;
        const int rr = idx >> 5, cc = idx & 31;
        const float v = tile[cc][rr];
        __half h = __float2half_rn(v);
        g_bth[(size_t)(c0 + rr) * NF + r0 + cc] = h;
        g_btl[(size_t)(c0 + rr) * NF + r0 + cc] =
            __float2half_rn(v - __half2float(h));
    }
}

// =====================================================================
// Tile copy: A (fp16), Bh, Bl — each 128 rows x 32 fp16, swizzled.
// =====================================================================
__device__ __forceinline__ void copy_tiles(
    uint32_t base, int tid,
    const __half* A, size_t ap,
    const __half* Bh, const __half* Bl, size_t bp) {
    #pragma unroll
    for (int p = 0; p < 2; ++p) {
        const int idx = tid + p * 256;       // 512 chunks
        const int r = idx >> 2, c = idx & 3;
        const uint32_t off = tswz(r, c);
        const size_t g = (size_t)r;
        cp16(base + OFF_A  + off, A  + g * ap + c * 8);
        cp16(base + OFF_BH + off, Bh + g * bp + c * 8);
        cp16(base + OFF_BL + off, Bl + g * bp + c * 8);
    }
    cp_commit();
}

// =====================================================================
// mainloop macro: BM=128 BN=128 BK=32, 8 warps (2Mx4N), warp tile 64x32,
// fp16 2-term split: A16*Bh + A16*Bl. 2 passes x 16 independent MMAs.
// 3-stage cp.async pipeline, one __syncthreads per iteration.
// =====================================================================
#define GEMM_MAINLOOP(sb, tid, A_, AP, Bh_, Bl_, BP, NT, acc)                         \
{                                                                                     \
    const int lane = (tid) & 31, warp = (tid) >> 5;                                   \
    const int wm = warp & 1, wn = warp >> 1;                                          \
    const int rsub = lane & 15, csub = lane >> 4;                                     \
    int arow[4], brow[2];                                                             \
    _Pragma("unroll") for (int i = 0; i < 4; ++i) arow[i] = wm * 64 + i * 16 + rsub;  \
    _Pragma("unroll") for (int j = 0; j < 2; ++j) brow[j] = wn * 32 + j * 16 + rsub;  \
    copy_tiles((sb), (tid), (A_), (AP), (Bh_), (Bl_), (BP));                          \
    copy_tiles((sb) + BUF_STRIDE, (tid),                                              \
               (A_) + 32, (AP), (Bh_) + 32, (Bl_) + 32, (BP));                        \
    int bufi = 0;                                                                     \
    for (int t = 0; t < (NT); ++t) {                                                  \
        const uint32_t cb_ = (sb) + (uint32_t)bufi * BUF_STRIDE;                      \
        if (t + 1 < (NT)) cp_wait1(); else cp_wait0();                                \
        __syncthreads();                                                              \
        if (t + 2 < (NT)) {                                                           \
            const int kc = (t + 2) * 32;                                              \
            int wbuf = bufi + 2; if (wbuf >= N_STAGES) wbuf -= N_STAGES;              \
            copy_tiles((sb) + (uint32_t)wbuf * BUF_STRIDE, (tid),                     \
                       (A_) + kc, (AP), (Bh_) + kc, (Bl_) + kc, (BP));                \
        }                                                                             \
        _Pragma("unroll") for (int h = 0; h < 2; ++h) {                               \
            uint32_t am[4][4], bh[2][4], bl[2][4];                                    \
            _Pragma("unroll") for (int i = 0; i < 4; ++i) {                           \
                const uint32_t ao = tswz(arow[i], 2 * h + csub);                      \
                ldsm4(am[i][0], am[i][1], am[i][2], am[i][3], cb_ + OFF_A + ao);      \
            }                                                                         \
            _Pragma("unroll") for (int j = 0; j < 2; ++j) {                           \
                const uint32_t bo = tswz(brow[j], 2 * h + csub);                      \
                ldsm4(bh[j][0], bh[j][1], bh[j][2], bh[j][3], cb_ + OFF_BH + bo);     \
                ldsm4(bl[j][0], bl[j][1], bl[j][2], bl[j][3], cb_ + OFF_BL + bo);     \
            }                                                                         \
            /* pass 1: A*Bh — 16 independent MMAs */                                  \
            _Pragma("unroll") for (int i = 0; i < 4; ++i)                             \
            _Pragma("unroll") for (int j2 = 0; j2 < 2; ++j2)                          \
            _Pragma("unroll") for (int s = 0; s < 2; ++s)                             \
                mma16816(acc[i][j2 * 2 + s], am[i], bh[j2][s], bh[j2][s + 2]);        \
            /* pass 2: A*Bl — 16 independent MMAs */                                  \
            _Pragma("unroll") for (int i = 0; i < 4; ++i)                             \
            _Pragma("unroll") for (int j2 = 0; j2 < 2; ++j2)                          \
            _Pragma("unroll") for (int s = 0; s < 2; ++s)                             \
                mma16816(acc[i][j2 * 2 + s], am[i], bl[j2][s], bl[j2][s + 2]);        \
        }                                                                             \
        if (++bufi >= N_STAGES) bufi = 0;                                             \
    }                                                                                 \
}

// =====================================================================
// Kernel 4: gemm2: partial[bz] = X[:,kslice] @ reps[kslice,:]  (split-K=8)
// =====================================================================
__global__ void __launch_bounds__(256, 2) gemm2_mm(void) {
    extern __shared__ char smem[];
    const uint32_t sb = smem_u32(smem);
    const int tid = threadIdx.x;
    const int bm = blockIdx.x, bn = blockIdx.y, bz = blockIdx.z;
    const int k0 = bz * (NF / SK2);
    const int NT = (NF / SK2) / 32;         // 32

    float acc[4][4][4];
    #pragma unroll
    for (int i = 0; i < 4; ++i)
        #pragma unroll
        for (int j = 0; j < 4; ++j)
            #pragma unroll
            for (int s = 0; s < 4; ++s) acc[i][j][s] = 0.0f;

    const __half* A  = g_xh  + (size_t)(bm * 128) * NF + k0;
    const __half* Bh = g_bth + (size_t)(bn * 128) * NF + k0;
    const __half* Bl = g_btl + (size_t)(bn * 128) * NF + k0;

    GEMM_MAINLOOP(sb, tid, A, NF, Bh, Bl, NF, NT, acc);

    const int lane = tid & 31, warp = tid >> 5;
    const int wm = warp & 1, wn = warp >> 1;
    float* P = g_part[bz];
    const int l4 = lane >> 2, l2 = (lane & 3) * 2;
    #pragma unroll
    for (int i = 0; i < 4; ++i) {
        const int r0 = bm * 128 + wm * 64 + i * 16 + l4;
        #pragma unroll
        for (int j = 0; j < 4; ++j) {
            const int n = bn * 128 + wn * 32 + j * 8 + l2;
            *(float2*)&P[(size_t)r0 * DIM + n]       = make_float2(acc[i][j][0], acc[i][j][1]);
            *(float2*)&P[(size_t)(r0 + 8) * DIM + n] = make_float2(acc[i][j][2], acc[i][j][3]);
        }
    }
}

// =====================================================================
// Kernel 5: sum split-K partials -> hidden fp16
// =====================================================================
__global__ void hconv_kernel() {
    const size_t i = ((size_t)blockIdx.x * 256 + threadIdx.x) * 4;
    float4 s = *(const float4*)&g_part[0][i];
    #pragma unroll
    for (int z = 1; z < SK2; ++z) {
        float4 p = *(const float4*)&g_part[z][i];
        s.x += p.x; s.y += p.y; s.z += p.z; s.w += p.w;
    }
    __half2 h01 = __floats2half2_rn(s.x, s.y);
    __half2 h23 = __floats2half2_rn(s.z, s.w);
    uint2 o;
    o.x = *(uint32_t*)&h01; o.y = *(uint32_t*)&h23;
    *(uint2*)&g_ah[i] = o;
}

// =====================================================================
// Kernel 6: gemm3: out = relu(hidden @ reps^T + bias)
// =====================================================================
__global__ void __launch_bounds__(256, 2) gemm3_mm(const float* __restrict__ bias,
                                                   float* __restrict__ out) {
    extern __shared__ char smem[];
    const uint32_t sb = smem_u32(smem);
    const int tid = threadIdx.x;
    const int bm = blockIdx.x, bn = blockIdx.y;
    const int NT = DIM / 32;                // 8

    float acc[4][4][4];
    #pragma unroll
    for (int i = 0; i < 4; ++i)
        #pragma unroll
        for (int j = 0; j < 4; ++j)
            #pragma unroll
            for (int s = 0; s < 4; ++s) acc[i][j][s] = 0.0f;

    const __half* A  = g_ah   + (size_t)(bm * 128) * DIM;
    const __half* Bh = g_bh16 + (size_t)(bn * 128) * DIM;
    const __half* Bl = g_bl16 + (size_t)(bn * 128) * DIM;

    GEMM_MAINLOOP(sb, tid, A, DIM, Bh, Bl, DIM, NT, acc);

    const int lane = tid & 31, warp = tid >> 5;
    const int wm = warp & 1, wn = warp >> 1;
    const int l4 = lane >> 2, l2 = (lane & 3) * 2;
    #pragma unroll
    for (int i = 0; i < 4; ++i) {
        const int r0 = bm * 128 + wm * 64 + i * 16 + l4;
        #pragma unroll
        for (int j = 0; j < 4; ++j) {
            const int n = bn * 128 + wn * 32 + j * 8 + l2;
            const float b0 = bias[n], b1 = bias[n + 1];
            float2 v0 = make_float2(fmaxf(acc[i][j][0] + b0, 0.0f),
                                    fmaxf(acc[i][j][1] + b1, 0.0f));
            float2 v1 = make_float2(fmaxf(acc[i][j][2] + b0, 0.0f),
                                    fmaxf(acc[i][j][3] + b1, 0.0f));
            *(float2*)&out[(size_t)r0 * NF + n]       = v0;
            *(float2*)&out[(size_t)(r0 + 8) * NF + n] = v1;
        }
    }
}

// =====================================================================
extern "C" void kernel_launch(void* const* d_in, const int* in_sizes, int n_in,
                              void* d_out, int out_size) {
    const float* x    = (const float*)d_in[0];
    const float* proj = (const float*)d_in[1];
    const float* rw   = (const float*)d_in[2];
    const float* rb   = (const float*)d_in[3];
    const float* cb   = (const float*)d_in[4];
    const float* bias = (const float*)d_in[5];
    float* out = (float*)d_out;

    const int wbytes = HEADS * CELLS * DIM * (int)sizeof(float);   // 128 KB
    cudaFuncSetAttribute((const void*)reps_kernel,
                         cudaFuncAttributeMaxDynamicSharedMemorySize, wbytes);
    cudaFuncSetAttribute((const void*)gemm2_mm,
                         cudaFuncAttributeMaxDynamicSharedMemorySize, GEMM_SMEM);
    cudaFuncSetAttribute((const void*)gemm3_mm,
                         cudaFuncAttributeMaxDynamicSharedMemorySize, GEMM_SMEM);

    cvtx_kernel<<<(int)(((size_t)BATCH * NF / 8) / 256), 256>>>(x);
    reps_kernel<<<148, 256, wbytes>>>(proj, rw, rb, cb);
    trans_kernel<<<dim3(NF / 32, DIM / 32), 256>>>();

    gemm2_mm<<<dim3(BATCH / 128, DIM / 128, SK2), 256, GEMM_SMEM>>>();
    hconv_kernel<<<(BATCH * DIM / 4) / 256, 256>>>();
    gemm3_mm<<<dim3(BATCH / 128, NF / 128), 256, GEMM_SMEM>>>(bias, out);
}

// round 12
// speedup vs baseline: 5.6277x; 1.2207x over previous
#include <cuda_runtime.h>
#include <cuda_fp16.h>
#include <cstdint>

#define BATCH 4096
#define NF    8192
#define DIM   256
#define HEADS 4
#define CELLS 32
#define SK2   8            // gemm2 split-K

// ---------------- scratch (device globals; no allocs allowed) ----------------
__device__ __align__(16) __half g_xh[(size_t)BATCH * NF];   // x fp16 (67 MB)
__device__ float g_reps[NF * DIM];
__device__ __align__(16) __half g_bh16[NF * DIM];           // reps   [NF][DIM] fp16
__device__ __align__(16) __half g_bth[DIM * NF];            // reps^T [DIM][NF] fp16
__device__ float g_part[SK2][(size_t)BATCH * DIM];
__device__ __align__(16) __half g_ah[BATCH * DIM];          // hidden fp16

// ---------------- PTX helpers (base ISA only) ----------------
__device__ __forceinline__ uint32_t smem_u32(const void* p) {
    uint32_t a;
    asm("{ .reg .u64 t; cvta.to.shared.u64 t, %1; cvt.u32.u64 %0, t; }" : "=r"(a) : "l"(p));
    return a;
}
__device__ __forceinline__ void cp16(uint32_t d, const void* s) {
    asm volatile("cp.async.cg.shared.global [%0], [%1], 16;" :: "r"(d), "l"(s));
}
__device__ __forceinline__ void cp_commit() {
    asm volatile("cp.async.commit_group;" ::: "memory");
}
__device__ __forceinline__ void cp_wait0() {
    asm volatile("cp.async.wait_group 0;" ::: "memory");
}
__device__ __forceinline__ void cp_wait1() {
    asm volatile("cp.async.wait_group 1;" ::: "memory");
}
__device__ __forceinline__ void ldsm4(uint32_t& r0, uint32_t& r1, uint32_t& r2,
                                      uint32_t& r3, uint32_t a) {
    asm("ldmatrix.sync.aligned.m8n8.x4.shared.b16 {%0,%1,%2,%3}, [%4];"
        : "=r"(r0), "=r"(r1), "=r"(r2), "=r"(r3) : "r"(a));
}
__device__ __forceinline__ void mma16816(float* d, const uint32_t* a,
                                         uint32_t b0, uint32_t b1) {
    asm("mma.sync.aligned.m16n8k16.row.col.f32.f16.f16.f32 "
        "{%0,%1,%2,%3}, {%4,%5,%6,%7}, {%8,%9}, {%0,%1,%2,%3};"
        : "+f"(d[0]), "+f"(d[1]), "+f"(d[2]), "+f"(d[3])
        : "r"(a[0]), "r"(a[1]), "r"(a[2]), "r"(a[3]), "r"(b0), "r"(b1));
}

// smem tile: 128 rows x 32 fp16 (4 16B chunks/row), chunk swizzle
#define OFF_A  0
#define OFF_B  8192
#define BUF_STRIDE 16384
#define N_STAGES 3
#define GEMM_SMEM (N_STAGES * BUF_STRIDE)    // 48 KB

__device__ __forceinline__ uint32_t tswz(int r, int c) {
    return (uint32_t)(r * 64 + ((c ^ ((r >> 1) & 3)) << 4));
}

// =====================================================================
// Kernel 1: reps (proven)
// =====================================================================
__global__ void reps_kernel(const float* __restrict__ proj,
                            const float* __restrict__ rw,
                            const float* __restrict__ rb,
                            const float* __restrict__ cb) {
    extern __shared__ float Wsh[];
    __shared__ float lat[DIM];
    __shared__ float sc[HEADS * CELLS];
    __shared__ float g_sh[HEADS];
    __shared__ int   w_sh[HEADS];
    __shared__ int   r_sh[HEADS];

    const int tid  = threadIdx.x;
    const int lane = tid & 31;
    const int warp = tid >> 5;

    for (int i = tid; i < HEADS * CELLS * DIM; i += 256)
        Wsh[i] = rw[i];
    __syncthreads();

    for (int row = blockIdx.x; row < NF; row += gridDim.x) {
        lat[tid] = proj[row * DIM + tid];
        __syncthreads();

        float la[8];
        #pragma unroll
        for (int i = 0; i < 8; ++i) la[i] = lat[lane + 32 * i];

        #pragma unroll 1
        for (int pi = 0; pi < 16; ++pi) {
            const int p = warp * 16 + pi;
            const float* wrow = &Wsh[p * DIM];
            float m = -3.4e38f;
            #pragma unroll
            for (int i = 0; i < 8; ++i)
                m = fmaxf(m, la[i] + wrow[lane + 32 * i]);
            #pragma unroll
            for (int off = 16; off >= 1; off >>= 1)
                m = fmaxf(m, __shfl_xor_sync(0xffffffffu, m, off));
            if (lane == 0) sc[p] = m + rb[p];
        }
        __syncthreads();

        if (warp < HEADS) {
            const float s = sc[warp * CELLS + lane];
            float v = s; int idx = lane;
            #pragma unroll
            for (int off = 16; off >= 1; off >>= 1) {
                float ov = __shfl_xor_sync(0xffffffffu, v, off);
                int   oi = __shfl_xor_sync(0xffffffffu, idx, off);
                if (ov > v || (ov == v && oi < idx)) { v = ov; idx = oi; }
            }
            const float v1 = v; const int i1 = idx;
            v = (lane == i1) ? -3.4e38f : s; idx = lane;
            #pragma unroll
            for (int off = 16; off >= 1; off >>= 1) {
                float ov = __shfl_xor_sync(0xffffffffu, v, off);
                int   oi = __shfl_xor_sync(0xffffffffu, idx, off);
                if (ov > v || (ov == v && oi < idx)) { v = ov; idx = oi; }
            }
            if (lane == 0) {
                g_sh[warp] = 1.0f / (1.0f + expf(-(v1 - v)));
                w_sh[warp] = i1;
                r_sh[warp] = idx;
            }
        }
        __syncthreads();

        float acc = lat[tid];
        #pragma unroll
        for (int h = 0; h < HEADS; ++h) {
            const float g = g_sh[h];
            acc += g          * cb[(h * CELLS + w_sh[h]) * DIM + tid]
                 + (1.0f - g) * cb[(h * CELLS + r_sh[h]) * DIM + tid];
        }
        g_reps[row * DIM + tid] = acc;
        __syncthreads();
    }
}

// =====================================================================
// Kernel 2: x -> fp16
// =====================================================================
__global__ void cvtx_kernel(const float* __restrict__ x) {
    const size_t i = ((size_t)blockIdx.x * 256 + threadIdx.x) * 8;
    float4 v0 = *(const float4*)(x + i);
    float4 v1 = *(const float4*)(x + i + 4);
    __half2 h01 = __floats2half2_rn(v0.x, v0.y);
    __half2 h23 = __floats2half2_rn(v0.z, v0.w);
    __half2 h45 = __floats2half2_rn(v1.x, v1.y);
    __half2 h67 = __floats2half2_rn(v1.z, v1.w);
    uint4 o;
    o.x = *(uint32_t*)&h01; o.y = *(uint32_t*)&h23;
    o.z = *(uint32_t*)&h45; o.w = *(uint32_t*)&h67;
    *(uint4*)&g_xh[i] = o;
}

// =====================================================================
// Kernel 3: reps -> fp16 (straight + transposed)
// =====================================================================
__global__ void trans_kernel() {
    __shared__ float tile[32][33];
    const int r0 = blockIdx.x * 32;     // NF dim
    const int c0 = blockIdx.y * 32;     // DIM dim
    const int tid = threadIdx.x;
    #pragma unroll
    for (int i = 0; i < 4; ++i) {
        const int idx = tid + i * 256;
        const int rr = idx >> 5, cc = idx & 31;
        const float v = g_reps[(r0 + rr) * DIM + c0 + cc];
        tile[rr][cc] = v;
        g_bh16[(r0 + rr) * DIM + c0 + cc] = __float2half_rn(v);
    }
    __syncthreads();
    #pragma unroll
    for (int i = 0; i < 4; ++i) {
        const int idx = tid + i * 256;
        const int rr = idx >> 5, cc = idx & 31;
        g_bth[(size_t)(c0 + rr) * NF + r0 + cc] = __float2half_rn(tile[cc][rr]);
    }
}

// =====================================================================
// Tile copy: A, B — each 128 rows x 32 fp16, swizzled. One commit group.
// =====================================================================
__device__ __forceinline__ void copy_tiles(
    uint32_t base, int tid,
    const __half* A, size_t ap,
    const __half* B, size_t bp) {
    #pragma unroll
    for (int p = 0; p < 2; ++p) {
        const int idx = tid + p * 256;       // 512 chunks
        const int r = idx >> 2, c = idx & 3;
        const uint32_t off = tswz(r, c);
        const size_t g = (size_t)r;
        cp16(base + OFF_A + off, A + g * ap + c * 8);
        cp16(base + OFF_B + off, B + g * bp + c * 8);
    }
    cp_commit();
}

// =====================================================================
// mainloop macro: BM=128 BN=128 BK=32, 8 warps (2Mx4N), warp tile 64x32,
// single-pass fp16. 16 independent MMAs per half-iter.
// 3-stage cp.async pipeline, one __syncthreads per iteration.
// =====================================================================
#define GEMM_MAINLOOP(sb, tid, A_, AP, B_, BP, NT, acc)                               \
{                                                                                     \
    const int lane = (tid) & 31, warp = (tid) >> 5;                                   \
    const int wm = warp & 1, wn = warp >> 1;                                          \
    const int rsub = lane & 15, csub = lane >> 4;                                     \
    int arow[4], brow[2];                                                             \
    _Pragma("unroll") for (int i = 0; i < 4; ++i) arow[i] = wm * 64 + i * 16 + rsub;  \
    _Pragma("unroll") for (int j = 0; j < 2; ++j) brow[j] = wn * 32 + j * 16 + rsub;  \
    copy_tiles((sb), (tid), (A_), (AP), (B_), (BP));                                  \
    copy_tiles((sb) + BUF_STRIDE, (tid), (A_) + 32, (AP), (B_) + 32, (BP));           \
    int bufi = 0;                                                                     \
    for (int t = 0; t < (NT); ++t) {                                                  \
        const uint32_t cb_ = (sb) + (uint32_t)bufi * BUF_STRIDE;                      \
        if (t + 1 < (NT)) cp_wait1(); else cp_wait0();                                \
        __syncthreads();                                                              \
        if (t + 2 < (NT)) {                                                           \
            const int kc = (t + 2) * 32;                                              \
            int wbuf = bufi + 2; if (wbuf >= N_STAGES) wbuf -= N_STAGES;              \
            copy_tiles((sb) + (uint32_t)wbuf * BUF_STRIDE, (tid),                     \
                       (A_) + kc, (AP), (B_) + kc, (BP));                             \
        }                                                                             \
        _Pragma("unroll") for (int h = 0; h < 2; ++h) {                               \
            uint32_t am[4][4], bm_[2][4];                                             \
            _Pragma("unroll") for (int i = 0; i < 4; ++i) {                           \
                const uint32_t ao = tswz(arow[i], 2 * h + csub);                      \
                ldsm4(am[i][0], am[i][1], am[i][2], am[i][3], cb_ + OFF_A + ao);      \
            }                                                                         \
            _Pragma("unroll") for (int j = 0; j < 2; ++j) {                           \
                const uint32_t bo = tswz(brow[j], 2 * h + csub);                      \
                ldsm4(bm_[j][0], bm_[j][1], bm_[j][2], bm_[j][3], cb_ + OFF_B + bo);  \
            }                                                                         \
            _Pragma("unroll") for (int i = 0; i < 4; ++i)                             \
            _Pragma("unroll") for (int j2 = 0; j2 < 2; ++j2)                          \
            _Pragma("unroll") for (int s = 0; s < 2; ++s)                             \
                mma16816(acc[i][j2 * 2 + s], am[i], bm_[j2][s], bm_[j2][s + 2]);      \
        }                                                                             \
        if (++bufi >= N_STAGES) bufi = 0;                                             \
    }                                                                                 \
}

// =====================================================================
// Kernel 4: gemm2: partial[bz] = X[:,kslice] @ reps[kslice,:]  (split-K=8)
// =====================================================================
__global__ void __launch_bounds__(256, 2) gemm2_mm(void) {
    extern __shared__ char smem[];
    const uint32_t sb = smem_u32(smem);
    const int tid = threadIdx.x;
    const int bm = blockIdx.x, bn = blockIdx.y, bz = blockIdx.z;
    const int k0 = bz * (NF / SK2);
    const int NT = (NF / SK2) / 32;         // 32

    float acc[4][4][4];
    #pragma unroll
    for (int i = 0; i < 4; ++i)
        #pragma unroll
        for (int j = 0; j < 4; ++j)
            #pragma unroll
            for (int s = 0; s < 4; ++s) acc[i][j][s] = 0.0f;

    const __half* A = g_xh  + (size_t)(bm * 128) * NF + k0;
    const __half* B = g_bth + (size_t)(bn * 128) * NF + k0;

    GEMM_MAINLOOP(sb, tid, A, NF, B, NF, NT, acc);

    const int lane = tid & 31, warp = tid >> 5;
    const int wm = warp & 1, wn = warp >> 1;
    float* P = g_part[bz];
    const int l4 = lane >> 2, l2 = (lane & 3) * 2;
    #pragma unroll
    for (int i = 0; i < 4; ++i) {
        const int r0 = bm * 128 + wm * 64 + i * 16 + l4;
        #pragma unroll
        for (int j = 0; j < 4; ++j) {
            const int n = bn * 128 + wn * 32 + j * 8 + l2;
            *(float2*)&P[(size_t)r0 * DIM + n]       = make_float2(acc[i][j][0], acc[i][j][1]);
            *(float2*)&P[(size_t)(r0 + 8) * DIM + n] = make_float2(acc[i][j][2], acc[i][j][3]);
        }
    }
}

// =====================================================================
// Kernel 5: sum split-K partials -> hidden fp16
// =====================================================================
__global__ void hconv_kernel() {
    const size_t i = ((size_t)blockIdx.x * 256 + threadIdx.x) * 4;
    float4 s = *(const float4*)&g_part[0][i];
    #pragma unroll
    for (int z = 1; z < SK2; ++z) {
        float4 p = *(const float4*)&g_part[z][i];
        s.x += p.x; s.y += p.y; s.z += p.z; s.w += p.w;
    }
    __half2 h01 = __floats2half2_rn(s.x, s.y);
    __half2 h23 = __floats2half2_rn(s.z, s.w);
    uint2 o;
    o.x = *(uint32_t*)&h01; o.y = *(uint32_t*)&h23;
    *(uint2*)&g_ah[i] = o;
}

// =====================================================================
// Kernel 6: gemm3: out = relu(hidden @ reps^T + bias)
// =====================================================================
__global__ void __launch_bounds__(256, 2) gemm3_mm(const float* __restrict__ bias,
                                                   float* __restrict__ out) {
    extern __shared__ char smem[];
    const uint32_t sb = smem_u32(smem);
    const int tid = threadIdx.x;
    const int bm = blockIdx.x, bn = blockIdx.y;
    const int NT = DIM / 32;                // 8

    float acc[4][4][4];
    #pragma unroll
    for (int i = 0; i < 4; ++i)
        #pragma unroll
        for (int j = 0; j < 4; ++j)
            #pragma unroll
            for (int s = 0; s < 4; ++s) acc[i][j][s] = 0.0f;

    const __half* A = g_ah   + (size_t)(bm * 128) * DIM;
    const __half* B = g_bh16 + (size_t)(bn * 128) * DIM;

    GEMM_MAINLOOP(sb, tid, A, DIM, B, DIM, NT, acc);

    const int lane = tid & 31, warp = tid >> 5;
    const int wm = warp & 1, wn = warp >> 1;
    const int l4 = lane >> 2, l2 = (lane & 3) * 2;
    #pragma unroll
    for (int i = 0; i < 4; ++i) {
        const int r0 = bm * 128 + wm * 64 + i * 16 + l4;
        #pragma unroll
        for (int j = 0; j < 4; ++j) {
            const int n = bn * 128 + wn * 32 + j * 8 + l2;
            const float b0 = bias[n], b1 = bias[n + 1];
            float2 v0 = make_float2(fmaxf(acc[i][j][0] + b0, 0.0f),
                                    fmaxf(acc[i][j][1] + b1, 0.0f));
            float2 v1 = make_float2(fmaxf(acc[i][j][2] + b0, 0.0f),
                                    fmaxf(acc[i][j][3] + b1, 0.0f));
            *(float2*)&out[(size_t)r0 * NF + n]       = v0;
            *(float2*)&out[(size_t)(r0 + 8) * NF + n] = v1;
        }
    }
}

// =====================================================================
extern "C" void kernel_launch(void* const* d_in, const int* in_sizes, int n_in,
                              void* d_out, int out_size) {
    const float* x    = (const float*)d_in[0];
    const float* proj = (const float*)d_in[1];
    const float* rw   = (const float*)d_in[2];
    const float* rb   = (const float*)d_in[3];
    const float* cb   = (const float*)d_in[4];
    const float* bias = (const float*)d_in[5];
    float* out = (float*)d_out;

    const int wbytes = HEADS * CELLS * DIM * (int)sizeof(float);   // 128 KB
    cudaFuncSetAttribute((const void*)reps_kernel,
                         cudaFuncAttributeMaxDynamicSharedMemorySize, wbytes);
    cudaFuncSetAttribute((const void*)gemm2_mm,
                         cudaFuncAttributeMaxDynamicSharedMemorySize, GEMM_SMEM);
    cudaFuncSetAttribute((const void*)gemm3_mm,
                         cudaFuncAttributeMaxDynamicSharedMemorySize, GEMM_SMEM);

    cvtx_kernel<<<(int)(((size_t)BATCH * NF / 8) / 256), 256>>>(x);
    reps_kernel<<<148, 256, wbytes>>>(proj, rw, rb, cb);
    trans_kernel<<<dim3(NF / 32, DIM / 32), 256>>>();

    gemm2_mm<<<dim3(BATCH / 128, DIM / 128, SK2), 256, GEMM_SMEM>>>();
    hconv_kernel<<<(BATCH * DIM / 4) / 256, 256>>>();
    gemm3_mm<<<dim3(BATCH / 128, NF / 128), 256, GEMM_SMEM>>>(bias, out);
}

// round 13
// speedup vs baseline: 6.8990x; 1.2259x over previous
#include <cuda_runtime.h>
#include <cuda_fp16.h>
#include <cstdint>

#define BATCH 4096
#define NF    8192
#define DIM   256
#define HEADS 4
#define CELLS 32
#define SK2   4            // gemm2 split-K

// ---------------- scratch (device globals; no allocs allowed) ----------------
__device__ __align__(16) __half g_xh[(size_t)BATCH * NF];   // x fp16 (67 MB)
__device__ float g_reps[NF * DIM];
__device__ __align__(16) __half g_bh16[NF * DIM];           // reps   [NF][DIM] fp16
__device__ __align__(16) __half g_bth[DIM * NF];            // reps^T [DIM][NF] fp16
__device__ float g_part[SK2][(size_t)BATCH * DIM];
__device__ __align__(16) __half g_ah[BATCH * DIM];          // hidden fp16

// ---------------- PTX helpers (base ISA only) ----------------
__device__ __forceinline__ uint32_t smem_u32(const void* p) {
    uint32_t a;
    asm("{ .reg .u64 t; cvta.to.shared.u64 t, %1; cvt.u32.u64 %0, t; }" : "=r"(a) : "l"(p));
    return a;
}
__device__ __forceinline__ void cp16(uint32_t d, const void* s) {
    asm volatile("cp.async.cg.shared.global [%0], [%1], 16;" :: "r"(d), "l"(s));
}
__device__ __forceinline__ void cp_commit() {
    asm volatile("cp.async.commit_group;" ::: "memory");
}
__device__ __forceinline__ void cp_wait0() {
    asm volatile("cp.async.wait_group 0;" ::: "memory");
}
__device__ __forceinline__ void cp_wait1() {
    asm volatile("cp.async.wait_group 1;" ::: "memory");
}
__device__ __forceinline__ void ldsm4(uint32_t& r0, uint32_t& r1, uint32_t& r2,
                                      uint32_t& r3, uint32_t a) {
    asm("ldmatrix.sync.aligned.m8n8.x4.shared.b16 {%0,%1,%2,%3}, [%4];"
        : "=r"(r0), "=r"(r1), "=r"(r2), "=r"(r3) : "r"(a));
}
__device__ __forceinline__ void mma16816(float* d, const uint32_t* a,
                                         uint32_t b0, uint32_t b1) {
    asm("mma.sync.aligned.m16n8k16.row.col.f32.f16.f16.f32 "
        "{%0,%1,%2,%3}, {%4,%5,%6,%7}, {%8,%9}, {%0,%1,%2,%3};"
        : "+f"(d[0]), "+f"(d[1]), "+f"(d[2]), "+f"(d[3])
        : "r"(a[0]), "r"(a[1]), "r"(a[2]), "r"(a[3]), "r"(b0), "r"(b1));
}

// smem tile: 128 rows x 32 fp16 (4 16B chunks/row), chunk swizzle
#define OFF_A  0
#define OFF_B  8192
#define BUF_STRIDE 16384
#define N_STAGES 3
#define GEMM_SMEM (N_STAGES * BUF_STRIDE)    // 48 KB

__device__ __forceinline__ uint32_t tswz(int r, int c) {
    return (uint32_t)(r * 64 + ((c ^ ((r >> 1) & 3)) << 4));
}

// =====================================================================
// Kernel 1: reps — smem partial-max reduction (no per-pair shuffles)
// =====================================================================
__global__ void reps_kernel(const float* __restrict__ proj,
                            const float* __restrict__ rw,
                            const float* __restrict__ rb,
                            const float* __restrict__ cb) {
    extern __shared__ float Wsh[];              // HEADS*CELLS*DIM floats (128KB)
    __shared__ float lat[DIM];
    __shared__ float part[HEADS * CELLS][33];   // padded: conflict-free finalize
    __shared__ float sc[HEADS * CELLS];
    __shared__ float g_sh[HEADS];
    __shared__ int   w_sh[HEADS];
    __shared__ int   r_sh[HEADS];

    const int tid  = threadIdx.x;
    const int lane = tid & 31;
    const int warp = tid >> 5;

    for (int i = tid; i < HEADS * CELLS * DIM; i += 256)
        Wsh[i] = rw[i];
    __syncthreads();

    for (int row = blockIdx.x; row < NF; row += gridDim.x) {
        lat[tid] = proj[row * DIM + tid];
        __syncthreads();

        float la[8];
        #pragma unroll
        for (int i = 0; i < 8; ++i) la[i] = lat[lane + 32 * i];

        // partial max per (pair, lane) -> smem (no shuffles)
        #pragma unroll 1
        for (int pi = 0; pi < 16; ++pi) {
            const int p = warp * 16 + pi;
            const float* wrow = &Wsh[p * DIM];
            float m = -3.4e38f;
            #pragma unroll
            for (int i = 0; i < 8; ++i)
                m = fmaxf(m, la[i] + wrow[lane + 32 * i]);
            part[p][lane] = m;
        }
        __syncthreads();

        // finalize: 128 threads each fold 32 partials serially
        if (tid < HEADS * CELLS) {
            float m = -3.4e38f;
            #pragma unroll
            for (int i = 0; i < 32; ++i) m = fmaxf(m, part[tid][i]);
            sc[tid] = m + rb[tid];
        }
        __syncthreads();

        // top-2 per head (warps 0..3), jax tie-break = lowest index
        if (warp < HEADS) {
            const float s = sc[warp * CELLS + lane];
            float v = s; int idx = lane;
            #pragma unroll
            for (int off = 16; off >= 1; off >>= 1) {
                float ov = __shfl_xor_sync(0xffffffffu, v, off);
                int   oi = __shfl_xor_sync(0xffffffffu, idx, off);
                if (ov > v || (ov == v && oi < idx)) { v = ov; idx = oi; }
            }
            const float v1 = v; const int i1 = idx;
            v = (lane == i1) ? -3.4e38f : s; idx = lane;
            #pragma unroll
            for (int off = 16; off >= 1; off >>= 1) {
                float ov = __shfl_xor_sync(0xffffffffu, v, off);
                int   oi = __shfl_xor_sync(0xffffffffu, idx, off);
                if (ov > v || (ov == v && oi < idx)) { v = ov; idx = oi; }
            }
            if (lane == 0) {
                g_sh[warp] = 1.0f / (1.0f + expf(-(v1 - v)));
                w_sh[warp] = i1;
                r_sh[warp] = idx;
            }
        }
        __syncthreads();

        float acc = lat[tid];
        #pragma unroll
        for (int h = 0; h < HEADS; ++h) {
            const float g = g_sh[h];
            acc += g          * cb[(h * CELLS + w_sh[h]) * DIM + tid]
                 + (1.0f - g) * cb[(h * CELLS + r_sh[h]) * DIM + tid];
        }
        g_reps[row * DIM + tid] = acc;
        g_bh16[row * DIM + tid] = __float2half_rn(acc);   // fused straight fp16
        __syncthreads();
    }
}

// =====================================================================
// Kernel 2: x -> fp16
// =====================================================================
__global__ void cvtx_kernel(const float* __restrict__ x) {
    const size_t i = ((size_t)blockIdx.x * 256 + threadIdx.x) * 8;
    float4 v0 = *(const float4*)(x + i);
    float4 v1 = *(const float4*)(x + i + 4);
    __half2 h01 = __floats2half2_rn(v0.x, v0.y);
    __half2 h23 = __floats2half2_rn(v0.z, v0.w);
    __half2 h45 = __floats2half2_rn(v1.x, v1.y);
    __half2 h67 = __floats2half2_rn(v1.z, v1.w);
    uint4 o;
    o.x = *(uint32_t*)&h01; o.y = *(uint32_t*)&h23;
    o.z = *(uint32_t*)&h45; o.w = *(uint32_t*)&h67;
    *(uint4*)&g_xh[i] = o;
}

// =====================================================================
// Kernel 3: reps -> fp16 transposed only
// =====================================================================
__global__ void trans_kernel() {
    __shared__ float tile[32][33];
    const int r0 = blockIdx.x * 32;     // NF dim
    const int c0 = blockIdx.y * 32;     // DIM dim
    const int tid = threadIdx.x;
    #pragma unroll
    for (int i = 0; i < 4; ++i) {
        const int idx = tid + i * 256;
        const int rr = idx >> 5, cc = idx & 31;
        tile[rr][cc] = g_reps[(r0 + rr) * DIM + c0 + cc];
    }
    __syncthreads();
    #pragma unroll
    for (int i = 0; i < 4; ++i) {
        const int idx = tid + i * 256;
        const int rr = idx >> 5, cc = idx & 31;
        g_bth[(size_t)(c0 + rr) * NF + r0 + cc] = __float2half_rn(tile[cc][rr]);
    }
}

// =====================================================================
// Tile copy: A, B — each 128 rows x 32 fp16, swizzled. One commit group.
// =====================================================================
__device__ __forceinline__ void copy_tiles(
    uint32_t base, int tid,
    const __half* A, size_t ap,
    const __half* B, size_t bp) {
    #pragma unroll
    for (int p = 0; p < 2; ++p) {
        const int idx = tid + p * 256;       // 512 chunks
        const int r = idx >> 2, c = idx & 3;
        const uint32_t off = tswz(r, c);
        const size_t g = (size_t)r;
        cp16(base + OFF_A + off, A + g * ap + c * 8);
        cp16(base + OFF_B + off, B + g * bp + c * 8);
    }
    cp_commit();
}

// =====================================================================
// mainloop macro: BM=128 BN=128 BK=32, 8 warps (2Mx4N), warp tile 64x32,
// single-pass fp16. 16 independent MMAs per half-iter.
// 3-stage cp.async pipeline, one __syncthreads per iteration.
// =====================================================================
#define GEMM_MAINLOOP(sb, tid, A_, AP, B_, BP, NT, acc)                               \
{                                                                                     \
    const int lane = (tid) & 31, warp = (tid) >> 5;                                   \
    const int wm = warp & 1, wn = warp >> 1;                                          \
    const int rsub = lane & 15, csub = lane >> 4;                                     \
    int arow[4], brow[2];                                                             \
    _Pragma("unroll") for (int i = 0; i < 4; ++i) arow[i] = wm * 64 + i * 16 + rsub;  \
    _Pragma("unroll") for (int j = 0; j < 2; ++j) brow[j] = wn * 32 + j * 16 + rsub;  \
    copy_tiles((sb), (tid), (A_), (AP), (B_), (BP));                                  \
    copy_tiles((sb) + BUF_STRIDE, (tid), (A_) + 32, (AP), (B_) + 32, (BP));           \
    int bufi = 0;                                                                     \
    for (int t = 0; t < (NT); ++t) {                                                  \
        const uint32_t cb_ = (sb) + (uint32_t)bufi * BUF_STRIDE;                      \
        if (t + 1 < (NT)) cp_wait1(); else cp_wait0();                                \
        __syncthreads();                                                              \
        if (t + 2 < (NT)) {                                                           \
            const int kc = (t + 2) * 32;                                              \
            int wbuf = bufi + 2; if (wbuf >= N_STAGES) wbuf -= N_STAGES;              \
            copy_tiles((sb) + (uint32_t)wbuf * BUF_STRIDE, (tid),                     \
                       (A_) + kc, (AP), (B_) + kc, (BP));                             \
        }                                                                             \
        _Pragma("unroll") for (int h = 0; h < 2; ++h) {                               \
            uint32_t am[4][4], bm_[2][4];                                             \
            _Pragma("unroll") for (int i = 0; i < 4; ++i) {                           \
                const uint32_t ao = tswz(arow[i], 2 * h + csub);                      \
                ldsm4(am[i][0], am[i][1], am[i][2], am[i][3], cb_ + OFF_A + ao);      \
            }                                                                         \
            _Pragma("unroll") for (int j = 0; j < 2; ++j) {                           \
                const uint32_t bo = tswz(brow[j], 2 * h + csub);                      \
                ldsm4(bm_[j][0], bm_[j][1], bm_[j][2], bm_[j][3], cb_ + OFF_B + bo);  \
            }                                                                         \
            _Pragma("unroll") for (int i = 0; i < 4; ++i)                             \
            _Pragma("unroll") for (int j2 = 0; j2 < 2; ++j2)                          \
            _Pragma("unroll") for (int s = 0; s < 2; ++s)                             \
                mma16816(acc[i][j2 * 2 + s], am[i], bm_[j2][s], bm_[j2][s + 2]);      \
        }                                                                             \
        if (++bufi >= N_STAGES) bufi = 0;                                             \
    }                                                                                 \
}

// =====================================================================
// Kernel 4: gemm2: partial[bz] = X[:,kslice] @ reps[kslice,:]  (split-K=4)
// =====================================================================
__global__ void __launch_bounds__(256, 2) gemm2_mm(void) {
    extern __shared__ char smem[];
    const uint32_t sb = smem_u32(smem);
    const int tid = threadIdx.x;
    const int bm = blockIdx.x, bn = blockIdx.y, bz = blockIdx.z;
    const int k0 = bz * (NF / SK2);
    const int NT = (NF / SK2) / 32;         // 64

    float acc[4][4][4];
    #pragma unroll
    for (int i = 0; i < 4; ++i)
        #pragma unroll
        for (int j = 0; j < 4; ++j)
            #pragma unroll
            for (int s = 0; s < 4; ++s) acc[i][j][s] = 0.0f;

    const __half* A = g_xh  + (size_t)(bm * 128) * NF + k0;
    const __half* B = g_bth + (size_t)(bn * 128) * NF + k0;

    GEMM_MAINLOOP(sb, tid, A, NF, B, NF, NT, acc);

    const int lane = tid & 31, warp = tid >> 5;
    const int wm = warp & 1, wn = warp >> 1;
    float* P = g_part[bz];
    const int l4 = lane >> 2, l2 = (lane & 3) * 2;
    #pragma unroll
    for (int i = 0; i < 4; ++i) {
        const int r0 = bm * 128 + wm * 64 + i * 16 + l4;
        #pragma unroll
        for (int j = 0; j < 4; ++j) {
            const int n = bn * 128 + wn * 32 + j * 8 + l2;
            *(float2*)&P[(size_t)r0 * DIM + n]       = make_float2(acc[i][j][0], acc[i][j][1]);
            *(float2*)&P[(size_t)(r0 + 8) * DIM + n] = make_float2(acc[i][j][2], acc[i][j][3]);
        }
    }
}

// =====================================================================
// Kernel 5: sum split-K partials -> hidden fp16
// =====================================================================
__global__ void hconv_kernel() {
    const size_t i = ((size_t)blockIdx.x * 256 + threadIdx.x) * 4;
    float4 s = *(const float4*)&g_part[0][i];
    #pragma unroll
    for (int z = 1; z < SK2; ++z) {
        float4 p = *(const float4*)&g_part[z][i];
        s.x += p.x; s.y += p.y; s.z += p.z; s.w += p.w;
    }
    __half2 h01 = __floats2half2_rn(s.x, s.y);
    __half2 h23 = __floats2half2_rn(s.z, s.w);
    uint2 o;
    o.x = *(uint32_t*)&h01; o.y = *(uint32_t*)&h23;
    *(uint2*)&g_ah[i] = o;
}

// =====================================================================
// Kernel 6: gemm3: out = relu(hidden @ reps^T + bias)
// =====================================================================
__global__ void __launch_bounds__(256, 2) gemm3_mm(const float* __restrict__ bias,
                                                   float* __restrict__ out) {
    extern __shared__ char smem[];
    const uint32_t sb = smem_u32(smem);
    const int tid = threadIdx.x;
    const int bm = blockIdx.x, bn = blockIdx.y;
    const int NT = DIM / 32;                // 8

    float acc[4][4][4];
    #pragma unroll
    for (int i = 0; i < 4; ++i)
        #pragma unroll
        for (int j = 0; j < 4; ++j)
            #pragma unroll
            for (int s = 0; s < 4; ++s) acc[i][j][s] = 0.0f;

    const __half* A = g_ah   + (size_t)(bm * 128) * DIM;
    const __half* B = g_bh16 + (size_t)(bn * 128) * DIM;

    GEMM_MAINLOOP(sb, tid, A, DIM, B, DIM, NT, acc);

    const int lane = tid & 31, warp = tid >> 5;
    const int wm = warp & 1, wn = warp >> 1;
    const int l4 = lane >> 2, l2 = (lane & 3) * 2;
    #pragma unroll
    for (int i = 0; i < 4; ++i) {
        const int r0 = bm * 128 + wm * 64 + i * 16 + l4;
        #pragma unroll
        for (int j = 0; j < 4; ++j) {
            const int n = bn * 128 + wn * 32 + j * 8 + l2;
            const float b0 = bias[n], b1 = bias[n + 1];
            float2 v0 = make_float2(fmaxf(acc[i][j][0] + b0, 0.0f),
                                    fmaxf(acc[i][j][1] + b1, 0.0f));
            float2 v1 = make_float2(fmaxf(acc[i][j][2] + b0, 0.0f),
                                    fmaxf(acc[i][j][3] + b1, 0.0f));
            *(float2*)&out[(size_t)r0 * NF + n]       = v0;
            *(float2*)&out[(size_t)(r0 + 8) * NF + n] = v1;
        }
    }
}

// =====================================================================
extern "C" void kernel_launch(void* const* d_in, const int* in_sizes, int n_in,
                              void* d_out, int out_size) {
    const float* x    = (const float*)d_in[0];
    const float* proj = (const float*)d_in[1];
    const float* rw   = (const float*)d_in[2];
    const float* rb   = (const float*)d_in[3];
    const float* cb   = (const float*)d_in[4];
    const float* bias = (const float*)d_in[5];
    float* out = (float*)d_out;

    const int wbytes = HEADS * CELLS * DIM * (int)sizeof(float);   // 128 KB
    cudaFuncSetAttribute((const void*)reps_kernel,
                         cudaFuncAttributeMaxDynamicSharedMemorySize, wbytes);
    cudaFuncSetAttribute((const void*)gemm2_mm,
                         cudaFuncAttributeMaxDynamicSharedMemorySize, GEMM_SMEM);
    cudaFuncSetAttribute((const void*)gemm3_mm,
                         cudaFuncAttributeMaxDynamicSharedMemorySize, GEMM_SMEM);

    cvtx_kernel<<<(int)(((size_t)BATCH * NF / 8) / 256), 256>>>(x);
    reps_kernel<<<148, 256, wbytes>>>(proj, rw, rb, cb);
    trans_kernel<<<dim3(NF / 32, DIM / 32), 256>>>();

    gemm2_mm<<<dim3(BATCH / 128, DIM / 128, SK2), 256, GEMM_SMEM>>>();
    hconv_kernel<<<(BATCH * DIM / 4) / 256, 256>>>();
    gemm3_mm<<<dim3(BATCH / 128, NF / 128), 256, GEMM_SMEM>>>(bias, out);
}

// round 14
// speedup vs baseline: 8.3982x; 1.2173x over previous
#include <cuda_runtime.h>
#include <cuda_fp16.h>
#include <cstdint>

#define BATCH 4096
#define NF    8192
#define DIM   256
#define HEADS 4
#define CELLS 32
#define SK2   4            // gemm2 split-K

// ---------------- scratch (device globals; no allocs allowed) ----------------
__device__ __align__(16) __half g_xh[(size_t)BATCH * NF];   // x fp16 (67 MB)
__device__ float g_reps[NF * DIM];
__device__ __align__(16) __half g_bh16[NF * DIM];           // reps   [NF][DIM] fp16
__device__ __align__(16) __half g_bth[DIM * NF];            // reps^T [DIM][NF] fp16
__device__ float g_part[SK2][(size_t)BATCH * DIM];
__device__ __align__(16) __half g_ah[BATCH * DIM];          // hidden fp16

// ---------------- PTX helpers (base ISA only) ----------------
__device__ __forceinline__ uint32_t smem_u32(const void* p) {
    uint32_t a;
    asm("{ .reg .u64 t; cvta.to.shared.u64 t, %1; cvt.u32.u64 %0, t; }" : "=r"(a) : "l"(p));
    return a;
}
__device__ __forceinline__ void cp16(uint32_t d, const void* s) {
    asm volatile("cp.async.cg.shared.global [%0], [%1], 16;" :: "r"(d), "l"(s));
}
__device__ __forceinline__ void cp_commit() {
    asm volatile("cp.async.commit_group;" ::: "memory");
}
__device__ __forceinline__ void cp_wait0() {
    asm volatile("cp.async.wait_group 0;" ::: "memory");
}
__device__ __forceinline__ void cp_wait1() {
    asm volatile("cp.async.wait_group 1;" ::: "memory");
}
__device__ __forceinline__ void ldsm4(uint32_t& r0, uint32_t& r1, uint32_t& r2,
                                      uint32_t& r3, uint32_t a) {
    asm("ldmatrix.sync.aligned.m8n8.x4.shared.b16 {%0,%1,%2,%3}, [%4];"
        : "=r"(r0), "=r"(r1), "=r"(r2), "=r"(r3) : "r"(a));
}
__device__ __forceinline__ void mma16816(float* d, const uint32_t* a,
                                         uint32_t b0, uint32_t b1) {
    asm("mma.sync.aligned.m16n8k16.row.col.f32.f16.f16.f32 "
        "{%0,%1,%2,%3}, {%4,%5,%6,%7}, {%8,%9}, {%0,%1,%2,%3};"
        : "+f"(d[0]), "+f"(d[1]), "+f"(d[2]), "+f"(d[3])
        : "r"(a[0]), "r"(a[1]), "r"(a[2]), "r"(a[3]), "r"(b0), "r"(b1));
}

// smem tile: 128 rows x 64 fp16 = 128 bytes/row (8 16B chunks), SW128 swizzle
// phys_chunk = c ^ (r & 7)  -> conflict-free for stores and all ldmatrix phases.
#define OFF_A  0
#define OFF_B  16384
#define BUF_STRIDE 32768
#define N_STAGES 3
#define GEMM_SMEM (N_STAGES * BUF_STRIDE)    // 96 KB

__device__ __forceinline__ uint32_t tswz(int r, int c) {
    return (uint32_t)(r * 128 + ((c ^ (r & 7)) << 4));
}

// =====================================================================
// Kernel 1: reps — 2 rows per pass (W loaded to regs once per pair),
// smem partial-max reduction, fused straight fp16 output.
// =====================================================================
__global__ void reps_kernel(const float* __restrict__ proj,
                            const float* __restrict__ rw,
                            const float* __restrict__ rb,
                            const float* __restrict__ cb) {
    extern __shared__ float Wsh[];              // HEADS*CELLS*DIM floats (128KB)
    __shared__ float lat[2][DIM];
    __shared__ float part[2][HEADS * CELLS][33];
    __shared__ float sc[2][HEADS * CELLS];
    __shared__ float g_sh[2][HEADS];
    __shared__ int   w_sh[2][HEADS];
    __shared__ int   r_sh[2][HEADS];

    const int tid  = threadIdx.x;
    const int lane = tid & 31;
    const int warp = tid >> 5;

    for (int i = tid; i < HEADS * CELLS * DIM; i += 256)
        Wsh[i] = rw[i];
    __syncthreads();

    for (int row = blockIdx.x * 2; row < NF; row += gridDim.x * 2) {
        lat[0][tid] = proj[row * DIM + tid];
        lat[1][tid] = proj[(row + 1) * DIM + tid];
        __syncthreads();

        float la0[8], la1[8];
        #pragma unroll
        for (int i = 0; i < 8; ++i) {
            la0[i] = lat[0][lane + 32 * i];
            la1[i] = lat[1][lane + 32 * i];
        }

        // partial max per (pair, lane) for BOTH rows; W read once per pair
        #pragma unroll 1
        for (int pi = 0; pi < 16; ++pi) {
            const int p = warp * 16 + pi;
            const float* wrow = &Wsh[p * DIM];
            float m0 = -3.4e38f, m1 = -3.4e38f;
            #pragma unroll
            for (int i = 0; i < 8; ++i) {
                const float w = wrow[lane + 32 * i];
                m0 = fmaxf(m0, la0[i] + w);
                m1 = fmaxf(m1, la1[i] + w);
            }
            part[0][p][lane] = m0;
            part[1][p][lane] = m1;
        }
        __syncthreads();

        // finalize: 256 threads: tid<128 row0, else row1
        {
            const int rsel = tid >> 7;          // 0 or 1
            const int p = tid & 127;
            float m = -3.4e38f;
            #pragma unroll
            for (int i = 0; i < 32; ++i) m = fmaxf(m, part[rsel][p][i]);
            sc[rsel][p] = m + rb[p];
        }
        __syncthreads();

        // top-2: 8 warps = (row, head) combos
        {
            const int rsel = warp >> 2, h = warp & 3;
            const float s = sc[rsel][h * CELLS + lane];
            float v = s; int idx = lane;
            #pragma unroll
            for (int off = 16; off >= 1; off >>= 1) {
                float ov = __shfl_xor_sync(0xffffffffu, v, off);
                int   oi = __shfl_xor_sync(0xffffffffu, idx, off);
                if (ov > v || (ov == v && oi < idx)) { v = ov; idx = oi; }
            }
            const float v1 = v; const int i1 = idx;
            v = (lane == i1) ? -3.4e38f : s; idx = lane;
            #pragma unroll
            for (int off = 16; off >= 1; off >>= 1) {
                float ov = __shfl_xor_sync(0xffffffffu, v, off);
                int   oi = __shfl_xor_sync(0xffffffffu, idx, off);
                if (ov > v || (ov == v && oi < idx)) { v = ov; idx = oi; }
            }
            if (lane == 0) {
                g_sh[rsel][h] = 1.0f / (1.0f + expf(-(v1 - v)));
                w_sh[rsel][h] = i1;
                r_sh[rsel][h] = idx;
            }
        }
        __syncthreads();

        #pragma unroll
        for (int rsel = 0; rsel < 2; ++rsel) {
            float acc = lat[rsel][tid];
            #pragma unroll
            for (int h = 0; h < HEADS; ++h) {
                const float g = g_sh[rsel][h];
                acc += g          * cb[(h * CELLS + w_sh[rsel][h]) * DIM + tid]
                     + (1.0f - g) * cb[(h * CELLS + r_sh[rsel][h]) * DIM + tid];
            }
            g_reps[(row + rsel) * DIM + tid] = acc;
            g_bh16[(row + rsel) * DIM + tid] = __float2half_rn(acc);
        }
        __syncthreads();
    }
}

// =====================================================================
// Kernel 2: x -> fp16
// =====================================================================
__global__ void cvtx_kernel(const float* __restrict__ x) {
    const size_t i = ((size_t)blockIdx.x * 256 + threadIdx.x) * 8;
    float4 v0 = *(const float4*)(x + i);
    float4 v1 = *(const float4*)(x + i + 4);
    __half2 h01 = __floats2half2_rn(v0.x, v0.y);
    __half2 h23 = __floats2half2_rn(v0.z, v0.w);
    __half2 h45 = __floats2half2_rn(v1.x, v1.y);
    __half2 h67 = __floats2half2_rn(v1.z, v1.w);
    uint4 o;
    o.x = *(uint32_t*)&h01; o.y = *(uint32_t*)&h23;
    o.z = *(uint32_t*)&h45; o.w = *(uint32_t*)&h67;
    *(uint4*)&g_xh[i] = o;
}

// =====================================================================
// Kernel 3: reps -> fp16 transposed only
// =====================================================================
__global__ void trans_kernel() {
    __shared__ float tile[32][33];
    const int r0 = blockIdx.x * 32;     // NF dim
    const int c0 = blockIdx.y * 32;     // DIM dim
    const int tid = threadIdx.x;
    #pragma unroll
    for (int i = 0; i < 4; ++i) {
        const int idx = tid + i * 256;
        const int rr = idx >> 5, cc = idx & 31;
        tile[rr][cc] = g_reps[(r0 + rr) * DIM + c0 + cc];
    }
    __syncthreads();
    #pragma unroll
    for (int i = 0; i < 4; ++i) {
        const int idx = tid + i * 256;
        const int rr = idx >> 5, cc = idx & 31;
        g_bth[(size_t)(c0 + rr) * NF + r0 + cc] = __float2half_rn(tile[cc][rr]);
    }
}

// =====================================================================
// Tile copy: A, B — each 128 rows x 64 fp16 (8 chunks/row), swizzled.
// =====================================================================
__device__ __forceinline__ void copy_tiles(
    uint32_t base, int tid,
    const __half* A, size_t ap,
    const __half* B, size_t bp) {
    #pragma unroll
    for (int p = 0; p < 4; ++p) {
        const int idx = tid + p * 256;       // 1024 chunks each
        const int r = idx >> 3, c = idx & 7;
        const uint32_t off = tswz(r, c);
        const size_t g = (size_t)r;
        cp16(base + OFF_A + off, A + g * ap + c * 8);
        cp16(base + OFF_B + off, B + g * bp + c * 8);
    }
    cp_commit();
}

// =====================================================================
// mainloop macro: BM=128 BN=128 BK=64, 8 warps (2Mx4N), warp tile 64x32,
// single-pass fp16. 4 h-steps x 16 independent MMAs per iteration.
// 3-stage cp.async pipeline, one __syncthreads per iteration.
// =====================================================================
#define GEMM_MAINLOOP(sb, tid, A_, AP, B_, BP, NT, acc)                               \
{                                                                                     \
    const int lane = (tid) & 31, warp = (tid) >> 5;                                   \
    const int wm = warp & 1, wn = warp >> 1;                                          \
    const int rsub = lane & 15, csub = lane >> 4;                                     \
    int arow[4], brow[2];                                                             \
    _Pragma("unroll") for (int i = 0; i < 4; ++i) arow[i] = wm * 64 + i * 16 + rsub;  \
    _Pragma("unroll") for (int j = 0; j < 2; ++j) brow[j] = wn * 32 + j * 16 + rsub;  \
    copy_tiles((sb), (tid), (A_), (AP), (B_), (BP));                                  \
    copy_tiles((sb) + BUF_STRIDE, (tid), (A_) + 64, (AP), (B_) + 64, (BP));           \
    int bufi = 0;                                                                     \
    for (int t = 0; t < (NT); ++t) {                                                  \
        const uint32_t cb_ = (sb) + (uint32_t)bufi * BUF_STRIDE;                      \
        if (t + 1 < (NT)) cp_wait1(); else cp_wait0();                                \
        __syncthreads();                                                              \
        if (t + 2 < (NT)) {                                                           \
            const int kc = (t + 2) * 64;                                              \
            int wbuf = bufi + 2; if (wbuf >= N_STAGES) wbuf -= N_STAGES;              \
            copy_tiles((sb) + (uint32_t)wbuf * BUF_STRIDE, (tid),                     \
                       (A_) + kc, (AP), (B_) + kc, (BP));                             \
        }                                                                             \
        _Pragma("unroll") for (int h = 0; h < 4; ++h) {                               \
            uint32_t am[4][4], bm_[2][4];                                             \
            _Pragma("unroll") for (int i = 0; i < 4; ++i) {                           \
                const uint32_t ao = tswz(arow[i], 2 * h + csub);                      \
                ldsm4(am[i][0], am[i][1], am[i][2], am[i][3], cb_ + OFF_A + ao);      \
            }                                                                         \
            _Pragma("unroll") for (int j = 0; j < 2; ++j) {                           \
                const uint32_t bo = tswz(brow[j], 2 * h + csub);                      \
                ldsm4(bm_[j][0], bm_[j][1], bm_[j][2], bm_[j][3], cb_ + OFF_B + bo);  \
            }                                                                         \
            _Pragma("unroll") for (int i = 0; i < 4; ++i)                             \
            _Pragma("unroll") for (int j2 = 0; j2 < 2; ++j2)                          \
            _Pragma("unroll") for (int s = 0; s < 2; ++s)                             \
                mma16816(acc[i][j2 * 2 + s], am[i], bm_[j2][s], bm_[j2][s + 2]);      \
        }                                                                             \
        if (++bufi >= N_STAGES) bufi = 0;                                             \
    }                                                                                 \
}

// =====================================================================
// Kernel 4: gemm2: partial[bz] = X[:,kslice] @ reps[kslice,:]  (split-K=4)
// =====================================================================
__global__ void __launch_bounds__(256, 2) gemm2_mm(void) {
    extern __shared__ char smem[];
    const uint32_t sb = smem_u32(smem);
    const int tid = threadIdx.x;
    const int bm = blockIdx.x, bn = blockIdx.y, bz = blockIdx.z;
    const int k0 = bz * (NF / SK2);
    const int NT = (NF / SK2) / 64;         // 32

    float acc[4][4][4];
    #pragma unroll
    for (int i = 0; i < 4; ++i)
        #pragma unroll
        for (int j = 0; j < 4; ++j)
            #pragma unroll
            for (int s = 0; s < 4; ++s) acc[i][j][s] = 0.0f;

    const __half* A = g_xh  + (size_t)(bm * 128) * NF + k0;
    const __half* B = g_bth + (size_t)(bn * 128) * NF + k0;

    GEMM_MAINLOOP(sb, tid, A, NF, B, NF, NT, acc);

    const int lane = tid & 31, warp = tid >> 5;
    const int wm = warp & 1, wn = warp >> 1;
    float* P = g_part[bz];
    const int l4 = lane >> 2, l2 = (lane & 3) * 2;
    #pragma unroll
    for (int i = 0; i < 4; ++i) {
        const int r0 = bm * 128 + wm * 64 + i * 16 + l4;
        #pragma unroll
        for (int j = 0; j < 4; ++j) {
            const int n = bn * 128 + wn * 32 + j * 8 + l2;
            *(float2*)&P[(size_t)r0 * DIM + n]       = make_float2(acc[i][j][0], acc[i][j][1]);
            *(float2*)&P[(size_t)(r0 + 8) * DIM + n] = make_float2(acc[i][j][2], acc[i][j][3]);
        }
    }
}

// =====================================================================
// Kernel 5: sum split-K partials -> hidden fp16
// =====================================================================
__global__ void hconv_kernel() {
    const size_t i = ((size_t)blockIdx.x * 256 + threadIdx.x) * 4;
    float4 s = *(const float4*)&g_part[0][i];
    #pragma unroll
    for (int z = 1; z < SK2; ++z) {
        float4 p = *(const float4*)&g_part[z][i];
        s.x += p.x; s.y += p.y; s.z += p.z; s.w += p.w;
    }
    __half2 h01 = __floats2half2_rn(s.x, s.y);
    __half2 h23 = __floats2half2_rn(s.z, s.w);
    uint2 o;
    o.x = *(uint32_t*)&h01; o.y = *(uint32_t*)&h23;
    *(uint2*)&g_ah[i] = o;
}

// =====================================================================
// Kernel 6: gemm3: out = relu(hidden @ reps^T + bias)
// =====================================================================
__global__ void __launch_bounds__(256, 2) gemm3_mm(const float* __restrict__ bias,
                                                   float* __restrict__ out) {
    extern __shared__ char smem[];
    const uint32_t sb = smem_u32(smem);
    const int tid = threadIdx.x;
    const int bm = blockIdx.x, bn = blockIdx.y;
    const int NT = DIM / 64;                // 4

    float acc[4][4][4];
    #pragma unroll
    for (int i = 0; i < 4; ++i)
        #pragma unroll
        for (int j = 0; j < 4; ++j)
            #pragma unroll
            for (int s = 0; s < 4; ++s) acc[i][j][s] = 0.0f;

    const __half* A = g_ah   + (size_t)(bm * 128) * DIM;
    const __half* B = g_bh16 + (size_t)(bn * 128) * DIM;

    GEMM_MAINLOOP(sb, tid, A, DIM, B, DIM, NT, acc);

    const int lane = tid & 31, warp = tid >> 5;
    const int wm = warp & 1, wn = warp >> 1;
    const int l4 = lane >> 2, l2 = (lane & 3) * 2;
    #pragma unroll
    for (int i = 0; i < 4; ++i) {
        const int r0 = bm * 128 + wm * 64 + i * 16 + l4;
        #pragma unroll
        for (int j = 0; j < 4; ++j) {
            const int n = bn * 128 + wn * 32 + j * 8 + l2;
            const float b0 = bias[n], b1 = bias[n + 1];
            float2 v0 = make_float2(fmaxf(acc[i][j][0] + b0, 0.0f),
                                    fmaxf(acc[i][j][1] + b1, 0.0f));
            float2 v1 = make_float2(fmaxf(acc[i][j][2] + b0, 0.0f),
                                    fmaxf(acc[i][j][3] + b1, 0.0f));
            *(float2*)&out[(size_t)r0 * NF + n]       = v0;
            *(float2*)&out[(size_t)(r0 + 8) * NF + n] = v1;
        }
    }
}

// =====================================================================
extern "C" void kernel_launch(void* const* d_in, const int* in_sizes, int n_in,
                              void* d_out, int out_size) {
    const float* x    = (const float*)d_in[0];
    const float* proj = (const float*)d_in[1];
    const float* rw   = (const float*)d_in[2];
    const float* rb   = (const float*)d_in[3];
    const float* cb   = (const float*)d_in[4];
    const float* bias = (const float*)d_in[5];
    float* out = (float*)d_out;

    const int wbytes = HEADS * CELLS * DIM * (int)sizeof(float);   // 128 KB
    cudaFuncSetAttribute((const void*)reps_kernel,
                         cudaFuncAttributeMaxDynamicSharedMemorySize, wbytes);
    cudaFuncSetAttribute((const void*)gemm2_mm,
                         cudaFuncAttributeMaxDynamicSharedMemorySize, GEMM_SMEM);
    cudaFuncSetAttribute((const void*)gemm3_mm,
                         cudaFuncAttributeMaxDynamicSharedMemorySize, GEMM_SMEM);

    cvtx_kernel<<<(int)(((size_t)BATCH * NF / 8) / 256), 256>>>(x);
    reps_kernel<<<148, 256, wbytes>>>(proj, rw, rb, cb);
    trans_kernel<<<dim3(NF / 32, DIM / 32), 256>>>();

    gemm2_mm<<<dim3(BATCH / 128, DIM / 128, SK2), 256, GEMM_SMEM>>>();
    hconv_kernel<<<(BATCH * DIM / 4) / 256, 256>>>();
    gemm3_mm<<<dim3(BATCH / 128, NF / 128), 256, GEMM_SMEM>>>(bias, out);
}